// round 4
// baseline (speedup 1.0000x reference)
#include <cuda_runtime.h>
#include <cstdint>
#include <cstddef>

#define N_BATCH 4
#define C_IN    256
#define HW      4096
#define E_DIM   128
#define OC      384   // 3*E

// ---------------- scratch (static device globals; no runtime allocation) ----------------
__device__ float g_qkv[(size_t)N_BATCH * OC * HW];         //  25.2 MB  (n, o, p) flat
__device__ float g_S[(size_t)N_BATCH * HW * HW];           // 268.4 MB  exp(scores)
__device__ float g_colpart[(size_t)N_BATCH * 32 * HW];     //   2.1 MB  per-i-block column partial sums
__device__ float g_colsum[(size_t)N_BATCH * HW];           //  64 KB
__device__ float g_VsT[(size_t)N_BATCH * E_DIM * HW];      //   8.4 MB  (n, d, j) = V^T / colsum
__device__ float g_O[(size_t)N_BATCH * HW * E_DIM];        //   8.4 MB  (n, i, d) flat

// ---------------- helpers ----------------
__device__ __forceinline__ uint32_t f2tf32(float x) {
    uint32_t r;
    asm("cvt.rna.tf32.f32 %0, %1;" : "=r"(r) : "f"(x));
    return r;
}

// fast exp for |x| <~ 2 : ~1e-7 relative error, pure FMA/ALU (avoids MUFU throughput wall)
__device__ __forceinline__ float fexp(float x) {
    float t = x * 1.4426950408889634f;        // x * log2(e)
    int   ri = __float2int_rn(t);
    float f = t - (float)ri;
    float u = f * 0.6931471805599453f;        // back to ln-space, |u| <= 0.3466
    float p = 1.3888889e-3f;                  // 1/720
    p = fmaf(p, u, 8.3333333e-3f);            // 1/120
    p = fmaf(p, u, 4.1666667e-2f);            // 1/24
    p = fmaf(p, u, 1.6666667e-1f);            // 1/6
    p = fmaf(p, u, 0.5f);
    p = fmaf(p, u, 1.0f);
    p = fmaf(p, u, 1.0f);
    return p * __int_as_float((ri + 127) << 23);
}

__device__ __forceinline__ void mma_tf32(float c[4],
                                         const uint32_t a[4],
                                         const uint32_t b[2]) {
    asm volatile(
        "mma.sync.aligned.m16n8k8.row.col.f32.tf32.tf32.f32 "
        "{%0,%1,%2,%3}, {%4,%5,%6,%7}, {%8,%9}, {%0,%1,%2,%3};"
        : "+f"(c[0]), "+f"(c[1]), "+f"(c[2]), "+f"(c[3])
        : "r"(a[0]), "r"(a[1]), "r"(a[2]), "r"(a[3]), "r"(b[0]), "r"(b[1]));
}

// ---------------- shared tiled GEMM core ----------------
// C[128 x 128] block. 256 threads = 8 warps, warp grid 4(M) x 2(N), warp tile 32x64.
// As/Bs stored [row][k] with row stride 20 words -> conflict-free fragment loads.
// B_KN=true : global B is [K][N] row-major (transposed while staging to smem)
// B_KN=false: global B is [N][K] row-major (natural .col operand)
template <bool B_KN>
__device__ __forceinline__ void gemm_main(
    const float* __restrict__ Abase, int lda,
    const float* __restrict__ Bbase, int ldb,
    int ktiles,
    uint32_t (*As)[20], uint32_t (*Bs)[20],
    float c[2][8][4], int tid)
{
    const int lane = tid & 31, warp = tid >> 5;
    const int gid = lane >> 2, tig = lane & 3;
    const int wm = warp & 3, wn = warp >> 2;

    for (int kt = 0; kt < ktiles; kt++) {
        const int k0 = kt * 16;
        // stage A tile [128 x 16]
#pragma unroll
        for (int i = 0; i < 2; i++) {
            int t = tid + 256 * i;
            int row = t >> 2, c4 = (t & 3) << 2;
            float4 v = __ldg(reinterpret_cast<const float4*>(
                Abase + (size_t)row * lda + k0 + c4));
            As[row][c4 + 0] = f2tf32(v.x);
            As[row][c4 + 1] = f2tf32(v.y);
            As[row][c4 + 2] = f2tf32(v.z);
            As[row][c4 + 3] = f2tf32(v.w);
        }
        // stage B tile
        if (B_KN) {
#pragma unroll
            for (int i = 0; i < 2; i++) {
                int t = tid + 256 * i;
                int k = t >> 5, c4 = (t & 31) << 2;
                float4 v = __ldg(reinterpret_cast<const float4*>(
                    Bbase + (size_t)(k0 + k) * ldb + c4));
                Bs[c4 + 0][k] = f2tf32(v.x);
                Bs[c4 + 1][k] = f2tf32(v.y);
                Bs[c4 + 2][k] = f2tf32(v.z);
                Bs[c4 + 3][k] = f2tf32(v.w);
            }
        } else {
#pragma unroll
            for (int i = 0; i < 2; i++) {
                int t = tid + 256 * i;
                int row = t >> 2, c4 = (t & 3) << 2;
                float4 v = __ldg(reinterpret_cast<const float4*>(
                    Bbase + (size_t)row * ldb + k0 + c4));
                Bs[row][c4 + 0] = f2tf32(v.x);
                Bs[row][c4 + 1] = f2tf32(v.y);
                Bs[row][c4 + 2] = f2tf32(v.z);
                Bs[row][c4 + 3] = f2tf32(v.w);
            }
        }
        __syncthreads();

#pragma unroll
        for (int kk = 0; kk < 2; kk++) {
            const int kb = kk << 3;
            uint32_t a[2][4];
#pragma unroll
            for (int ms = 0; ms < 2; ms++) {
                int rb = wm * 32 + ms * 16;
                a[ms][0] = As[rb + gid][kb + tig];
                a[ms][1] = As[rb + gid + 8][kb + tig];
                a[ms][2] = As[rb + gid][kb + tig + 4];
                a[ms][3] = As[rb + gid + 8][kb + tig + 4];
            }
            uint32_t b[8][2];
#pragma unroll
            for (int ns = 0; ns < 8; ns++) {
                int nb = wn * 64 + ns * 8;
                b[ns][0] = Bs[nb + gid][kb + tig];
                b[ns][1] = Bs[nb + gid][kb + tig + 4];
            }
#pragma unroll
            for (int ms = 0; ms < 2; ms++)
#pragma unroll
                for (int ns = 0; ns < 8; ns++)
                    mma_tf32(c[ms][ns], a[ms], b[ns]);
        }
        __syncthreads();
    }
}

// ---------------- K1: QKV projection -------------------------------------
// qkv[n,o,p] = sum_c Wqkv[o,c] * x[n,c,p] + bqkv[o]
__global__ void __launch_bounds__(256, 2) k_qkv(
    const float* __restrict__ x, const float* __restrict__ Wqkv,
    const float* __restrict__ bqkv)
{
    __shared__ uint32_t As[128][20];
    __shared__ uint32_t Bs[128][20];
    const int n = blockIdx.z;
    const int m0 = blockIdx.y * 128;   // output channel block (384/128 = 3)
    const int p0 = blockIdx.x * 128;   // spatial block
    const float* Abase = Wqkv + (size_t)m0 * C_IN;               // [M][K]
    const float* Bbase = x + (size_t)n * C_IN * HW + p0;         // [K][N]
    float c[2][8][4] = {};
    gemm_main<true>(Abase, C_IN, Bbase, HW, C_IN / 16, As, Bs, c, threadIdx.x);

    const int lane = threadIdx.x & 31, warp = threadIdx.x >> 5;
    const int gid = lane >> 2, tig = lane & 3, wm = warp & 3, wn = warp >> 2;
    float* Cb = g_qkv + (size_t)n * OC * HW;
#pragma unroll
    for (int ms = 0; ms < 2; ms++) {
        const int r0 = m0 + wm * 32 + ms * 16 + gid;
        const float b0 = bqkv[r0], b1 = bqkv[r0 + 8];
#pragma unroll
        for (int ns = 0; ns < 8; ns++) {
            const int col = p0 + wn * 64 + ns * 8 + 2 * tig;
            *(float2*)(Cb + (size_t)r0 * HW + col) =
                make_float2(c[ms][ns][0] + b0, c[ms][ns][1] + b0);
            *(float2*)(Cb + (size_t)(r0 + 8) * HW + col) =
                make_float2(c[ms][ns][2] + b1, c[ms][ns][3] + b1);
        }
    }
}

// ---------------- K2: S' = exp(Q K^T / 64), column partial sums ----------
// Q[i,k] = qkv_flat[i*384 + k], K[j,k] = qkv_flat[j*384 + 128 + k]
__global__ void __launch_bounds__(256, 2) k_scores()
{
    __shared__ uint32_t As[128][20];
    __shared__ uint32_t Bs[128][20];
    const int n = blockIdx.z;
    const int i0 = blockIdx.y * 128;
    const int j0 = blockIdx.x * 128;
    const float* qb = g_qkv + (size_t)n * OC * HW;
    const float* Abase = qb + (size_t)i0 * 384;          // Q rows   [M][K] ld 384
    const float* Bbase = qb + (size_t)j0 * 384 + 128;    // K rows   [N][K] ld 384
    float c[2][8][4] = {};
    gemm_main<false>(Abase, 384, Bbase, 384, 128 / 16, As, Bs, c, threadIdx.x);

    const int lane = threadIdx.x & 31, warp = threadIdx.x >> 5;
    const int gid = lane >> 2, tig = lane & 3, wm = warp & 3, wn = warp >> 2;
    float* Sb = g_S + (size_t)n * HW * HW;
    const float scale = 0.015625f;  // 1/sqrt(4096)
    float csum[8][2];
#pragma unroll
    for (int ns = 0; ns < 8; ns++) { csum[ns][0] = 0.f; csum[ns][1] = 0.f; }

#pragma unroll
    for (int ms = 0; ms < 2; ms++) {
        const int r0 = i0 + wm * 32 + ms * 16 + gid;
#pragma unroll
        for (int ns = 0; ns < 8; ns++) {
            const int col = j0 + wn * 64 + ns * 8 + 2 * tig;
            float e0 = fexp(c[ms][ns][0] * scale);
            float e1 = fexp(c[ms][ns][1] * scale);
            float e2 = fexp(c[ms][ns][2] * scale);
            float e3 = fexp(c[ms][ns][3] * scale);
            *(float2*)(Sb + (size_t)r0 * HW + col)       = make_float2(e0, e1);
            *(float2*)(Sb + (size_t)(r0 + 8) * HW + col) = make_float2(e2, e3);
            csum[ns][0] += e0 + e2;
            csum[ns][1] += e1 + e3;
        }
    }
    // deterministic column reduction: shfl across row-groups, smem across warps
    float* part = (float*)As;  // [4 warpsM][128 cols]; smem free after gemm's final sync
#pragma unroll
    for (int ns = 0; ns < 8; ns++) {
#pragma unroll
        for (int jj = 0; jj < 2; jj++) {
            float v = csum[ns][jj];
            v += __shfl_xor_sync(0xffffffffu, v, 4);
            v += __shfl_xor_sync(0xffffffffu, v, 8);
            v += __shfl_xor_sync(0xffffffffu, v, 16);
            if (gid == 0)
                part[wm * 128 + wn * 64 + ns * 8 + 2 * tig + jj] = v;
        }
    }
    __syncthreads();
    const int t = threadIdx.x;
    if (t < 128) {
        float s = part[t] + part[128 + t] + part[256 + t] + part[384 + t];
        g_colpart[((size_t)n * 32 + blockIdx.y) * HW + j0 + t] = s;
    }
}

// ---------------- K2b: reduce column partials -> colsum -------------------
__global__ void k_colreduce()
{
    const int idx = blockIdx.x * 256 + threadIdx.x;   // over N*HW = 16384
    const int n = idx >> 12;
    const int j = idx & 4095;
    float s = 0.f;
#pragma unroll
    for (int b = 0; b < 32; b++)
        s += g_colpart[((size_t)n * 32 + b) * HW + j];
    g_colsum[idx] = s;
}

// ---------------- K3: VsT[d][j] = V[j,d] / colsum[j] (transpose) ----------
__global__ void k_vscale()
{
    __shared__ float t[32][33];
    const int n = blockIdx.z;
    const int j0 = blockIdx.x * 32;
    const int d0 = blockIdx.y * 32;
    const int tx = threadIdx.x, ty = threadIdx.y;
    const float* qb = g_qkv + (size_t)n * OC * HW;
    t[ty][tx] = qb[(size_t)(j0 + ty) * 384 + 256 + d0 + tx];
    __syncthreads();
    const int j = j0 + tx;
    g_VsT[((size_t)n * E_DIM + d0 + ty) * HW + j] = t[tx][ty] / g_colsum[n * HW + j];
}

// ---------------- K4: O = S' @ VsT^T --------------------------------------
__global__ void __launch_bounds__(256, 2) k_pv()
{
    __shared__ uint32_t As[128][20];
    __shared__ uint32_t Bs[128][20];
    const int n = blockIdx.z;
    const int i0 = blockIdx.y * 128;
    const float* Abase = g_S + (size_t)n * HW * HW + (size_t)i0 * HW;  // [M][K] ld 4096
    const float* Bbase = g_VsT + (size_t)n * E_DIM * HW;               // [N=128][K] ld 4096
    float c[2][8][4] = {};
    gemm_main<false>(Abase, HW, Bbase, HW, HW / 16, As, Bs, c, threadIdx.x);

    const int lane = threadIdx.x & 31, warp = threadIdx.x >> 5;
    const int gid = lane >> 2, tig = lane & 3, wm = warp & 3, wn = warp >> 2;
    float* Ob = g_O + (size_t)n * HW * E_DIM;
#pragma unroll
    for (int ms = 0; ms < 2; ms++) {
        const int r0 = i0 + wm * 32 + ms * 16 + gid;
#pragma unroll
        for (int ns = 0; ns < 8; ns++) {
            const int col = wn * 64 + ns * 8 + 2 * tig;
            *(float2*)(Ob + (size_t)r0 * E_DIM + col) =
                make_float2(c[ms][ns][0], c[ms][ns][1]);
            *(float2*)(Ob + (size_t)(r0 + 8) * E_DIM + col) =
                make_float2(c[ms][ns][2], c[ms][ns][3]);
        }
    }
}

// ---------------- K5: output projection -----------------------------------
// y[n,c,p] = sum_e Wout[c,e] * Oflat[n][e*4096 + p] + bout[c]
__global__ void __launch_bounds__(256, 2) k_proj(
    float* __restrict__ out, const float* __restrict__ Wout,
    const float* __restrict__ bout)
{
    __shared__ uint32_t As[128][20];
    __shared__ uint32_t Bs[128][20];
    const int n = blockIdx.z;
    const int c0 = blockIdx.y * 128;   // 256/128 = 2
    const int p0 = blockIdx.x * 128;
    const float* Abase = Wout + (size_t)c0 * E_DIM;              // [M][K] ld 128
    const float* Bbase = g_O + (size_t)n * HW * E_DIM + p0;      // [K=128][N] ld 4096
    float c[2][8][4] = {};
    gemm_main<true>(Abase, E_DIM, Bbase, HW, E_DIM / 16, As, Bs, c, threadIdx.x);

    const int lane = threadIdx.x & 31, warp = threadIdx.x >> 5;
    const int gid = lane >> 2, tig = lane & 3, wm = warp & 3, wn = warp >> 2;
    float* Yb = out + (size_t)n * C_IN * HW;
#pragma unroll
    for (int ms = 0; ms < 2; ms++) {
        const int r0 = c0 + wm * 32 + ms * 16 + gid;
        const float b0 = bout[r0], b1 = bout[r0 + 8];
#pragma unroll
        for (int ns = 0; ns < 8; ns++) {
            const int col = p0 + wn * 64 + ns * 8 + 2 * tig;
            *(float2*)(Yb + (size_t)r0 * HW + col) =
                make_float2(c[ms][ns][0] + b0, c[ms][ns][1] + b0);
            *(float2*)(Yb + (size_t)(r0 + 8) * HW + col) =
                make_float2(c[ms][ns][2] + b1, c[ms][ns][3] + b1);
        }
    }
}

// ---------------- launch ---------------------------------------------------
extern "C" void kernel_launch(void* const* d_in, const int* in_sizes, int n_in,
                              void* d_out, int out_size)
{
    (void)in_sizes; (void)n_in; (void)out_size;
    const float* x    = (const float*)d_in[0];
    const float* Wqkv = (const float*)d_in[1];
    const float* bqkv = (const float*)d_in[2];
    const float* Wout = (const float*)d_in[3];
    const float* bout = (const float*)d_in[4];
    float* out = (float*)d_out;

    dim3 blk(256);
    k_qkv<<<dim3(HW / 128, OC / 128, N_BATCH), blk>>>(x, Wqkv, bqkv);
    k_scores<<<dim3(HW / 128, HW / 128, N_BATCH), blk>>>();
    k_colreduce<<<(N_BATCH * HW) / 256, 256>>>();
    k_vscale<<<dim3(HW / 32, E_DIM / 32, N_BATCH), dim3(32, 32)>>>();
    k_pv<<<dim3(1, HW / 128, N_BATCH), blk>>>();
    k_proj<<<dim3(HW / 128, C_IN / 128, N_BATCH), blk>>>(out, Wout, bout);
}

// round 5
// speedup vs baseline: 1.2524x; 1.2524x over previous
#include <cuda_runtime.h>
#include <cstdint>
#include <cstddef>

#define N_BATCH 4
#define C_IN    256
#define HW      4096
#define E_DIM   128
#define OC      384   // 3*E

// ---------------- scratch (static device globals; no runtime allocation) ----------------
__device__ float g_qkv[(size_t)N_BATCH * OC * HW];         //  25.2 MB  (n, o, p) flat, tf32-rounded
__device__ float g_S[(size_t)N_BATCH * HW * HW];           // 268.4 MB  exp(scores), tf32-rounded
__device__ float g_colpart[(size_t)N_BATCH * 32 * HW];     //   2.1 MB  per-i-block column partial sums
__device__ float g_colsum[(size_t)N_BATCH * HW];           //  64 KB
__device__ float g_VsT[(size_t)N_BATCH * E_DIM * HW];      //   8.4 MB  (n, d, j) = V^T / colsum, tf32-rounded
__device__ float g_O[(size_t)N_BATCH * HW * E_DIM];        //   8.4 MB  (n, i, d) flat

// ---------------- helpers ----------------
__device__ __forceinline__ uint32_t f2tf32(float x) {
    uint32_t r;
    asm("cvt.rna.tf32.f32 %0, %1;" : "=r"(r) : "f"(x));
    return r;
}
__device__ __forceinline__ float round_tf32(float x) {
    return __uint_as_float(f2tf32(x));
}

// fast exp for |x| <~ 2 : ~1e-7 relative error, pure FMA/ALU (avoids MUFU throughput wall)
__device__ __forceinline__ float fexp(float x) {
    float t = x * 1.4426950408889634f;
    int   ri = __float2int_rn(t);
    float f = t - (float)ri;
    float u = f * 0.6931471805599453f;
    float p = 1.3888889e-3f;
    p = fmaf(p, u, 8.3333333e-3f);
    p = fmaf(p, u, 4.1666667e-2f);
    p = fmaf(p, u, 1.6666667e-1f);
    p = fmaf(p, u, 0.5f);
    p = fmaf(p, u, 1.0f);
    p = fmaf(p, u, 1.0f);
    return p * __int_as_float((ri + 127) << 23);
}

__device__ __forceinline__ void mma_tf32(float c[4],
                                         const uint32_t a[4],
                                         const uint32_t b[2]) {
    asm volatile(
        "mma.sync.aligned.m16n8k8.row.col.f32.tf32.tf32.f32 "
        "{%0,%1,%2,%3}, {%4,%5,%6,%7}, {%8,%9}, {%0,%1,%2,%3};"
        : "+f"(c[0]), "+f"(c[1]), "+f"(c[2]), "+f"(c[3])
        : "r"(a[0]), "r"(a[1]), "r"(a[2]), "r"(a[3]), "r"(b[0]), "r"(b[1]));
}

// cp.async 16B helpers
__device__ __forceinline__ void cp16(void* smem_dst, const void* gsrc) {
    uint32_t s = (uint32_t)__cvta_generic_to_shared(smem_dst);
    asm volatile("cp.async.cg.shared.global [%0], [%1], 16;\n" :: "r"(s), "l"(gsrc));
}
__device__ __forceinline__ void cp_commit() {
    asm volatile("cp.async.commit_group;\n");
}
template <int N>
__device__ __forceinline__ void cp_wait() {
    asm volatile("cp.async.wait_group %0;\n" :: "n"(N));
}

// ================= async double-buffered GEMM core ========================
// C[128 x 128] block, 256 threads = 8 warps, warp grid 4(M) x 2(N), tile 32x64.
// A global [M][K], B global [N][K]; data in global is ALREADY tf32-rounded
// (rounded by producing kernel's epilogue) so cp.async needs no conversion.
// Smem row stride 20 floats = 80 B -> every 16B group 16B-aligned, conflict-free.
__device__ __forceinline__ void gemm_async(
    const float* __restrict__ Abase, int lda,
    const float* __restrict__ Bbase, int ldb,
    int ktiles,
    float (*As)[128][20], float (*Bs)[128][20],
    float c[2][8][4], int tid)
{
    const int lane = tid & 31, warp = tid >> 5;
    const int gid = lane >> 2, tig = lane & 3;
    const int wm = warp & 3, wn = warp >> 2;
    const int r0 = tid >> 2, c4 = (tid & 3) << 2;  // staging coords (rows r0, r0+64)

    auto issue = [&](int kt, int buf) {
        const int k0 = kt * 16;
        cp16(&As[buf][r0][c4],      Abase + (size_t)r0 * lda + k0 + c4);
        cp16(&As[buf][r0 + 64][c4], Abase + (size_t)(r0 + 64) * lda + k0 + c4);
        cp16(&Bs[buf][r0][c4],      Bbase + (size_t)r0 * ldb + k0 + c4);
        cp16(&Bs[buf][r0 + 64][c4], Bbase + (size_t)(r0 + 64) * ldb + k0 + c4);
        cp_commit();
    };

    issue(0, 0);
    for (int kt = 0; kt < ktiles; kt++) {
        const int buf = kt & 1;
        if (kt + 1 < ktiles) { issue(kt + 1, (kt + 1) & 1); cp_wait<1>(); }
        else                 { cp_wait<0>(); }
        __syncthreads();

#pragma unroll
        for (int kk = 0; kk < 2; kk++) {
            const int kb = kk << 3;
            uint32_t a[2][4];
#pragma unroll
            for (int ms = 0; ms < 2; ms++) {
                int rb = wm * 32 + ms * 16;
                a[ms][0] = __float_as_uint(As[buf][rb + gid][kb + tig]);
                a[ms][1] = __float_as_uint(As[buf][rb + gid + 8][kb + tig]);
                a[ms][2] = __float_as_uint(As[buf][rb + gid][kb + tig + 4]);
                a[ms][3] = __float_as_uint(As[buf][rb + gid + 8][kb + tig + 4]);
            }
            uint32_t b[8][2];
#pragma unroll
            for (int ns = 0; ns < 8; ns++) {
                int nb = wn * 64 + ns * 8;
                b[ns][0] = __float_as_uint(Bs[buf][nb + gid][kb + tig]);
                b[ns][1] = __float_as_uint(Bs[buf][nb + gid][kb + tig + 4]);
            }
#pragma unroll
            for (int ms = 0; ms < 2; ms++)
#pragma unroll
                for (int ns = 0; ns < 8; ns++)
                    mma_tf32(c[ms][ns], a[ms], b[ns]);
        }
        __syncthreads();
    }
}

// ================= LDG+cvt GEMM core (external fp32 inputs) ===============
// B_KN=true : global B is [K][N] row-major (transposed while staging to smem)
template <bool B_KN>
__device__ __forceinline__ void gemm_main(
    const float* __restrict__ Abase, int lda,
    const float* __restrict__ Bbase, int ldb,
    int ktiles,
    uint32_t (*As)[20], uint32_t (*Bs)[20],
    float c[2][8][4], int tid)
{
    const int lane = tid & 31, warp = tid >> 5;
    const int gid = lane >> 2, tig = lane & 3;
    const int wm = warp & 3, wn = warp >> 2;

    for (int kt = 0; kt < ktiles; kt++) {
        const int k0 = kt * 16;
#pragma unroll
        for (int i = 0; i < 2; i++) {
            int t = tid + 256 * i;
            int row = t >> 2, c4 = (t & 3) << 2;
            float4 v = __ldg(reinterpret_cast<const float4*>(
                Abase + (size_t)row * lda + k0 + c4));
            As[row][c4 + 0] = f2tf32(v.x);
            As[row][c4 + 1] = f2tf32(v.y);
            As[row][c4 + 2] = f2tf32(v.z);
            As[row][c4 + 3] = f2tf32(v.w);
        }
        if (B_KN) {
#pragma unroll
            for (int i = 0; i < 2; i++) {
                int t = tid + 256 * i;
                int k = t >> 5, c4 = (t & 31) << 2;
                float4 v = __ldg(reinterpret_cast<const float4*>(
                    Bbase + (size_t)(k0 + k) * ldb + c4));
                Bs[c4 + 0][k] = f2tf32(v.x);
                Bs[c4 + 1][k] = f2tf32(v.y);
                Bs[c4 + 2][k] = f2tf32(v.z);
                Bs[c4 + 3][k] = f2tf32(v.w);
            }
        } else {
#pragma unroll
            for (int i = 0; i < 2; i++) {
                int t = tid + 256 * i;
                int row = t >> 2, c4 = (t & 3) << 2;
                float4 v = __ldg(reinterpret_cast<const float4*>(
                    Bbase + (size_t)row * ldb + k0 + c4));
                Bs[row][c4 + 0] = f2tf32(v.x);
                Bs[row][c4 + 1] = f2tf32(v.y);
                Bs[row][c4 + 2] = f2tf32(v.z);
                Bs[row][c4 + 3] = f2tf32(v.w);
            }
        }
        __syncthreads();

#pragma unroll
        for (int kk = 0; kk < 2; kk++) {
            const int kb = kk << 3;
            uint32_t a[2][4];
#pragma unroll
            for (int ms = 0; ms < 2; ms++) {
                int rb = wm * 32 + ms * 16;
                a[ms][0] = As[rb + gid][kb + tig];
                a[ms][1] = As[rb + gid + 8][kb + tig];
                a[ms][2] = As[rb + gid][kb + tig + 4];
                a[ms][3] = As[rb + gid + 8][kb + tig + 4];
            }
            uint32_t b[8][2];
#pragma unroll
            for (int ns = 0; ns < 8; ns++) {
                int nb = wn * 64 + ns * 8;
                b[ns][0] = Bs[nb + gid][kb + tig];
                b[ns][1] = Bs[nb + gid][kb + tig + 4];
            }
#pragma unroll
            for (int ms = 0; ms < 2; ms++)
#pragma unroll
                for (int ns = 0; ns < 8; ns++)
                    mma_tf32(c[ms][ns], a[ms], b[ns]);
        }
        __syncthreads();
    }
}

// ---------------- K1: QKV projection (stores tf32-rounded) ----------------
// qkv[n,o,p] = sum_c Wqkv[o,c] * x[n,c,p] + bqkv[o]
__global__ void __launch_bounds__(256, 2) k_qkv(
    const float* __restrict__ x, const float* __restrict__ Wqkv,
    const float* __restrict__ bqkv)
{
    __shared__ uint32_t As[128][20];
    __shared__ uint32_t Bs[128][20];
    const int n = blockIdx.z;
    const int m0 = blockIdx.y * 128;
    const int p0 = blockIdx.x * 128;
    const float* Abase = Wqkv + (size_t)m0 * C_IN;               // [M][K]
    const float* Bbase = x + (size_t)n * C_IN * HW + p0;         // [K][N]
    float c[2][8][4] = {};
    gemm_main<true>(Abase, C_IN, Bbase, HW, C_IN / 16, As, Bs, c, threadIdx.x);

    const int lane = threadIdx.x & 31, warp = threadIdx.x >> 5;
    const int gid = lane >> 2, tig = lane & 3, wm = warp & 3, wn = warp >> 2;
    float* Cb = g_qkv + (size_t)n * OC * HW;
#pragma unroll
    for (int ms = 0; ms < 2; ms++) {
        const int r0 = m0 + wm * 32 + ms * 16 + gid;
        const float b0 = bqkv[r0], b1 = bqkv[r0 + 8];
#pragma unroll
        for (int ns = 0; ns < 8; ns++) {
            const int col = p0 + wn * 64 + ns * 8 + 2 * tig;
            *(float2*)(Cb + (size_t)r0 * HW + col) =
                make_float2(round_tf32(c[ms][ns][0] + b0), round_tf32(c[ms][ns][1] + b0));
            *(float2*)(Cb + (size_t)(r0 + 8) * HW + col) =
                make_float2(round_tf32(c[ms][ns][2] + b1), round_tf32(c[ms][ns][3] + b1));
        }
    }
}

// ---------------- K2: S' = exp(Q K^T / 64), column partial sums ----------
// Q[i,k] = qkv_flat[i*384 + k], K[j,k] = qkv_flat[j*384 + 128 + k]
__global__ void __launch_bounds__(256, 2) k_scores()
{
    __shared__ float As[2][128][20];
    __shared__ float Bs[2][128][20];
    const int n = blockIdx.z;
    const int i0 = blockIdx.y * 128;
    const int j0 = blockIdx.x * 128;
    const float* qb = g_qkv + (size_t)n * OC * HW;
    const float* Abase = qb + (size_t)i0 * 384;          // Q rows   [M][K] ld 384
    const float* Bbase = qb + (size_t)j0 * 384 + 128;    // K rows   [N][K] ld 384
    float c[2][8][4] = {};
    gemm_async(Abase, 384, Bbase, 384, 128 / 16, As, Bs, c, threadIdx.x);

    const int lane = threadIdx.x & 31, warp = threadIdx.x >> 5;
    const int gid = lane >> 2, tig = lane & 3, wm = warp & 3, wn = warp >> 2;
    float* Sb = g_S + (size_t)n * HW * HW;
    const float scale = 0.015625f;  // 1/sqrt(4096)
    float csum[8][2];
#pragma unroll
    for (int ns = 0; ns < 8; ns++) { csum[ns][0] = 0.f; csum[ns][1] = 0.f; }

#pragma unroll
    for (int ms = 0; ms < 2; ms++) {
        const int r0 = i0 + wm * 32 + ms * 16 + gid;
#pragma unroll
        for (int ns = 0; ns < 8; ns++) {
            const int col = j0 + wn * 64 + ns * 8 + 2 * tig;
            // round exp to tf32 HERE so k_pv can cp.async raw bits; sum the
            // rounded values so colsum matches the stored matrix exactly.
            float e0 = round_tf32(fexp(c[ms][ns][0] * scale));
            float e1 = round_tf32(fexp(c[ms][ns][1] * scale));
            float e2 = round_tf32(fexp(c[ms][ns][2] * scale));
            float e3 = round_tf32(fexp(c[ms][ns][3] * scale));
            *(float2*)(Sb + (size_t)r0 * HW + col)       = make_float2(e0, e1);
            *(float2*)(Sb + (size_t)(r0 + 8) * HW + col) = make_float2(e2, e3);
            csum[ns][0] += e0 + e2;
            csum[ns][1] += e1 + e3;
        }
    }
    // deterministic column reduction: shfl across row-groups, smem across warps
    float* part = (float*)As;  // smem free after gemm's final sync
#pragma unroll
    for (int ns = 0; ns < 8; ns++) {
#pragma unroll
        for (int jj = 0; jj < 2; jj++) {
            float v = csum[ns][jj];
            v += __shfl_xor_sync(0xffffffffu, v, 4);
            v += __shfl_xor_sync(0xffffffffu, v, 8);
            v += __shfl_xor_sync(0xffffffffu, v, 16);
            if (gid == 0)
                part[wm * 128 + wn * 64 + ns * 8 + 2 * tig + jj] = v;
        }
    }
    __syncthreads();
    const int t = threadIdx.x;
    if (t < 128) {
        float s = part[t] + part[128 + t] + part[256 + t] + part[384 + t];
        g_colpart[((size_t)n * 32 + blockIdx.y) * HW + j0 + t] = s;
    }
}

// ---------------- K2b: reduce column partials -> colsum -------------------
__global__ void k_colreduce()
{
    const int idx = blockIdx.x * 256 + threadIdx.x;   // over N*HW = 16384
    const int n = idx >> 12;
    const int j = idx & 4095;
    float s = 0.f;
#pragma unroll
    for (int b = 0; b < 32; b++)
        s += g_colpart[((size_t)n * 32 + b) * HW + j];
    g_colsum[idx] = s;
}

// ---------------- K3: VsT[d][j] = tf32(V[j,d] / colsum[j]) ----------------
__global__ void k_vscale()
{
    __shared__ float t[32][33];
    const int n = blockIdx.z;
    const int j0 = blockIdx.x * 32;
    const int d0 = blockIdx.y * 32;
    const int tx = threadIdx.x, ty = threadIdx.y;
    const float* qb = g_qkv + (size_t)n * OC * HW;
    t[ty][tx] = qb[(size_t)(j0 + ty) * 384 + 256 + d0 + tx];
    __syncthreads();
    const int j = j0 + tx;
    g_VsT[((size_t)n * E_DIM + d0 + ty) * HW + j] =
        round_tf32(t[tx][ty] / g_colsum[n * HW + j]);
}

// ---------------- K4: O = S' @ VsT^T --------------------------------------
__global__ void __launch_bounds__(256, 2) k_pv()
{
    __shared__ float As[2][128][20];
    __shared__ float Bs[2][128][20];
    const int n = blockIdx.z;
    const int i0 = blockIdx.y * 128;
    const float* Abase = g_S + (size_t)n * HW * HW + (size_t)i0 * HW;  // [M][K] ld 4096
    const float* Bbase = g_VsT + (size_t)n * E_DIM * HW;               // [N=128][K] ld 4096
    float c[2][8][4] = {};
    gemm_async(Abase, HW, Bbase, HW, HW / 16, As, Bs, c, threadIdx.x);

    const int lane = threadIdx.x & 31, warp = threadIdx.x >> 5;
    const int gid = lane >> 2, tig = lane & 3, wm = warp & 3, wn = warp >> 2;
    float* Ob = g_O + (size_t)n * HW * E_DIM;
#pragma unroll
    for (int ms = 0; ms < 2; ms++) {
        const int r0 = i0 + wm * 32 + ms * 16 + gid;
#pragma unroll
        for (int ns = 0; ns < 8; ns++) {
            const int col = wn * 64 + ns * 8 + 2 * tig;
            *(float2*)(Ob + (size_t)r0 * E_DIM + col) =
                make_float2(c[ms][ns][0], c[ms][ns][1]);
            *(float2*)(Ob + (size_t)(r0 + 8) * E_DIM + col) =
                make_float2(c[ms][ns][2], c[ms][ns][3]);
        }
    }
}

// ---------------- K5: output projection -----------------------------------
// y[n,c,p] = sum_e Wout[c,e] * Oflat[n][e*4096 + p] + bout[c]
__global__ void __launch_bounds__(256, 2) k_proj(
    float* __restrict__ out, const float* __restrict__ Wout,
    const float* __restrict__ bout)
{
    __shared__ uint32_t As[128][20];
    __shared__ uint32_t Bs[128][20];
    const int n = blockIdx.z;
    const int c0 = blockIdx.y * 128;
    const int p0 = blockIdx.x * 128;
    const float* Abase = Wout + (size_t)c0 * E_DIM;              // [M][K] ld 128
    const float* Bbase = g_O + (size_t)n * HW * E_DIM + p0;      // [K=128][N] ld 4096
    float c[2][8][4] = {};
    gemm_main<true>(Abase, E_DIM, Bbase, HW, E_DIM / 16, As, Bs, c, threadIdx.x);

    const int lane = threadIdx.x & 31, warp = threadIdx.x >> 5;
    const int gid = lane >> 2, tig = lane & 3, wm = warp & 3, wn = warp >> 2;
    float* Yb = out + (size_t)n * C_IN * HW;
#pragma unroll
    for (int ms = 0; ms < 2; ms++) {
        const int r0 = c0 + wm * 32 + ms * 16 + gid;
        const float b0 = bout[r0], b1 = bout[r0 + 8];
#pragma unroll
        for (int ns = 0; ns < 8; ns++) {
            const int col = p0 + wn * 64 + ns * 8 + 2 * tig;
            *(float2*)(Yb + (size_t)r0 * HW + col) =
                make_float2(c[ms][ns][0] + b0, c[ms][ns][1] + b0);
            *(float2*)(Yb + (size_t)(r0 + 8) * HW + col) =
                make_float2(c[ms][ns][2] + b1, c[ms][ns][3] + b1);
        }
    }
}

// ---------------- launch ---------------------------------------------------
extern "C" void kernel_launch(void* const* d_in, const int* in_sizes, int n_in,
                              void* d_out, int out_size)
{
    (void)in_sizes; (void)n_in; (void)out_size;
    const float* x    = (const float*)d_in[0];
    const float* Wqkv = (const float*)d_in[1];
    const float* bqkv = (const float*)d_in[2];
    const float* Wout = (const float*)d_in[3];
    const float* bout = (const float*)d_in[4];
    float* out = (float*)d_out;

    dim3 blk(256);
    k_qkv<<<dim3(HW / 128, OC / 128, N_BATCH), blk>>>(x, Wqkv, bqkv);
    k_scores<<<dim3(HW / 128, HW / 128, N_BATCH), blk>>>();
    k_colreduce<<<(N_BATCH * HW) / 256, 256>>>();
    k_vscale<<<dim3(HW / 32, E_DIM / 32, N_BATCH), dim3(32, 32)>>>();
    k_pv<<<dim3(1, HW / 128, N_BATCH), blk>>>();
    k_proj<<<dim3(HW / 128, C_IN / 128, N_BATCH), blk>>>(out, Wout, bout);
}

// round 6
// speedup vs baseline: 1.6201x; 1.2936x over previous
#include <cuda_runtime.h>
#include <cuda_fp16.h>
#include <cstdint>
#include <cstddef>

#define N_BATCH 4
#define C_IN    256
#define HW      4096
#define E_DIM   128
#define OC      384   // 3*E
#define KSPLIT  2
#define VS_SCALE 256.0f
#define VS_INV   0.00390625f

// ---------------- scratch (static device globals; no runtime allocation) ----------------
__device__ float  g_qkv[(size_t)N_BATCH * OC * HW];          //  25.2 MB (n,o,p) flat, tf32-rounded
__device__ __half g_S[(size_t)N_BATCH * HW * HW];            // 134.2 MB exp(scores), fp16
__device__ float  g_colpart[(size_t)N_BATCH * 32 * HW];      //   2.1 MB per-i-block column partials
__device__ float  g_colsum[(size_t)N_BATCH * HW];            //  64 KB
__device__ __half g_VsT[(size_t)N_BATCH * E_DIM * HW];       //   4.2 MB (n,d,j) = 256*V^T/colsum, fp16
__device__ float  g_Opart[(size_t)KSPLIT * N_BATCH * HW * E_DIM]; // 16.8 MB split-K partials

// ---------------- helpers ----------------
__device__ __forceinline__ uint32_t f2tf32(float x) {
    uint32_t r;
    asm("cvt.rna.tf32.f32 %0, %1;" : "=r"(r) : "f"(x));
    return r;
}
__device__ __forceinline__ float round_tf32(float x) {
    return __uint_as_float(f2tf32(x));
}

// fast exp for |x| <~ 2 : ~1e-7 relative error, pure FMA/ALU (avoids MUFU throughput wall)
__device__ __forceinline__ float fexp(float x) {
    float t = x * 1.4426950408889634f;
    int   ri = __float2int_rn(t);
    float f = t - (float)ri;
    float u = f * 0.6931471805599453f;
    float p = 1.3888889e-3f;
    p = fmaf(p, u, 8.3333333e-3f);
    p = fmaf(p, u, 4.1666667e-2f);
    p = fmaf(p, u, 1.6666667e-1f);
    p = fmaf(p, u, 0.5f);
    p = fmaf(p, u, 1.0f);
    p = fmaf(p, u, 1.0f);
    return p * __int_as_float((ri + 127) << 23);
}

__device__ __forceinline__ void mma_tf32(float c[4],
                                         const uint32_t a[4],
                                         const uint32_t b[2]) {
    asm volatile(
        "mma.sync.aligned.m16n8k8.row.col.f32.tf32.tf32.f32 "
        "{%0,%1,%2,%3}, {%4,%5,%6,%7}, {%8,%9}, {%0,%1,%2,%3};"
        : "+f"(c[0]), "+f"(c[1]), "+f"(c[2]), "+f"(c[3])
        : "r"(a[0]), "r"(a[1]), "r"(a[2]), "r"(a[3]), "r"(b[0]), "r"(b[1]));
}
__device__ __forceinline__ void mma_f16(float c[4],
                                        const uint32_t a[4],
                                        const uint32_t b[2]) {
    asm volatile(
        "mma.sync.aligned.m16n8k16.row.col.f32.f16.f16.f32 "
        "{%0,%1,%2,%3}, {%4,%5,%6,%7}, {%8,%9}, {%0,%1,%2,%3};"
        : "+f"(c[0]), "+f"(c[1]), "+f"(c[2]), "+f"(c[3])
        : "r"(a[0]), "r"(a[1]), "r"(a[2]), "r"(a[3]), "r"(b[0]), "r"(b[1]));
}

// cp.async 16B helpers
__device__ __forceinline__ void cp16(void* smem_dst, const void* gsrc) {
    uint32_t s = (uint32_t)__cvta_generic_to_shared(smem_dst);
    asm volatile("cp.async.cg.shared.global [%0], [%1], 16;\n" :: "r"(s), "l"(gsrc));
}
__device__ __forceinline__ void cp_commit() {
    asm volatile("cp.async.commit_group;\n");
}
template <int N>
__device__ __forceinline__ void cp_wait() {
    asm volatile("cp.async.wait_group %0;\n" :: "n"(N));
}

// ================= async double-buffered tf32 GEMM core (fp32 data) =======
// C[128x128], 256 threads = 8 warps 4(M)x2(N), warp tile 32x64, k-tile 16.
// Global data already tf32-rounded by producer epilogues.
__device__ __forceinline__ void gemm_async(
    const float* __restrict__ Abase, int lda,
    const float* __restrict__ Bbase, int ldb,
    int ktiles,
    float (*As)[128][20], float (*Bs)[128][20],
    float c[2][8][4], int tid)
{
    const int lane = tid & 31, warp = tid >> 5;
    const int gid = lane >> 2, tig = lane & 3;
    const int wm = warp & 3, wn = warp >> 2;
    const int r0 = tid >> 2, c4 = (tid & 3) << 2;

    auto issue = [&](int kt, int buf) {
        const int k0 = kt * 16;
        cp16(&As[buf][r0][c4],      Abase + (size_t)r0 * lda + k0 + c4);
        cp16(&As[buf][r0 + 64][c4], Abase + (size_t)(r0 + 64) * lda + k0 + c4);
        cp16(&Bs[buf][r0][c4],      Bbase + (size_t)r0 * ldb + k0 + c4);
        cp16(&Bs[buf][r0 + 64][c4], Bbase + (size_t)(r0 + 64) * ldb + k0 + c4);
        cp_commit();
    };

    issue(0, 0);
    for (int kt = 0; kt < ktiles; kt++) {
        const int buf = kt & 1;
        if (kt + 1 < ktiles) { issue(kt + 1, (kt + 1) & 1); cp_wait<1>(); }
        else                 { cp_wait<0>(); }
        __syncthreads();

#pragma unroll
        for (int kk = 0; kk < 2; kk++) {
            const int kb = kk << 3;
            uint32_t a[2][4];
#pragma unroll
            for (int ms = 0; ms < 2; ms++) {
                int rb = wm * 32 + ms * 16;
                a[ms][0] = __float_as_uint(As[buf][rb + gid][kb + tig]);
                a[ms][1] = __float_as_uint(As[buf][rb + gid + 8][kb + tig]);
                a[ms][2] = __float_as_uint(As[buf][rb + gid][kb + tig + 4]);
                a[ms][3] = __float_as_uint(As[buf][rb + gid + 8][kb + tig + 4]);
            }
            uint32_t b[8][2];
#pragma unroll
            for (int ns = 0; ns < 8; ns++) {
                int nb = wn * 64 + ns * 8;
                b[ns][0] = __float_as_uint(Bs[buf][nb + gid][kb + tig]);
                b[ns][1] = __float_as_uint(Bs[buf][nb + gid][kb + tig + 4]);
            }
#pragma unroll
            for (int ms = 0; ms < 2; ms++)
#pragma unroll
                for (int ns = 0; ns < 8; ns++)
                    mma_tf32(c[ms][ns], a[ms], b[ns]);
        }
        __syncthreads();
    }
}

// ================= async double-buffered fp16 GEMM core ====================
// C[128x128] fp32 accum, A/B fp16 [row][k] global, k-tile 32.
// Smem row stride 40 halfs (80B): 16B-aligned cp.async dsts, conflict-free frags.
__device__ __forceinline__ void gemm_async_f16(
    const __half* __restrict__ Abase, int lda,
    const __half* __restrict__ Bbase, int ldb,
    int ktiles,
    __half (*As)[128][40], __half (*Bs)[128][40],
    float c[2][8][4], int tid)
{
    const int lane = tid & 31, warp = tid >> 5;
    const int gid = lane >> 2, tig = lane & 3;
    const int wm = warp & 3, wn = warp >> 2;
    const int r0 = tid >> 2, h8 = (tid & 3) << 3;  // 8 halfs = 16 B per cp

    auto issue = [&](int kt, int buf) {
        const int k0 = kt * 32;
        cp16(&As[buf][r0][h8],      Abase + (size_t)r0 * lda + k0 + h8);
        cp16(&As[buf][r0 + 64][h8], Abase + (size_t)(r0 + 64) * lda + k0 + h8);
        cp16(&Bs[buf][r0][h8],      Bbase + (size_t)r0 * ldb + k0 + h8);
        cp16(&Bs[buf][r0 + 64][h8], Bbase + (size_t)(r0 + 64) * ldb + k0 + h8);
        cp_commit();
    };

    issue(0, 0);
    for (int kt = 0; kt < ktiles; kt++) {
        const int buf = kt & 1;
        if (kt + 1 < ktiles) { issue(kt + 1, (kt + 1) & 1); cp_wait<1>(); }
        else                 { cp_wait<0>(); }
        __syncthreads();

#pragma unroll
        for (int kk = 0; kk < 2; kk++) {
            const int kb = kk << 4;
            uint32_t a[2][4];
#pragma unroll
            for (int ms = 0; ms < 2; ms++) {
                int rb = wm * 32 + ms * 16;
                a[ms][0] = *(const uint32_t*)&As[buf][rb + gid][kb + 2 * tig];
                a[ms][1] = *(const uint32_t*)&As[buf][rb + gid + 8][kb + 2 * tig];
                a[ms][2] = *(const uint32_t*)&As[buf][rb + gid][kb + 2 * tig + 8];
                a[ms][3] = *(const uint32_t*)&As[buf][rb + gid + 8][kb + 2 * tig + 8];
            }
            uint32_t b[8][2];
#pragma unroll
            for (int ns = 0; ns < 8; ns++) {
                int nb = wn * 64 + ns * 8;
                b[ns][0] = *(const uint32_t*)&Bs[buf][nb + gid][kb + 2 * tig];
                b[ns][1] = *(const uint32_t*)&Bs[buf][nb + gid][kb + 2 * tig + 8];
            }
#pragma unroll
            for (int ms = 0; ms < 2; ms++)
#pragma unroll
                for (int ns = 0; ns < 8; ns++)
                    mma_f16(c[ms][ns], a[ms], b[ns]);
        }
        __syncthreads();
    }
}

// ================= LDG+cvt GEMM core (external fp32 inputs) ===============
// B_KN=true : global B is [K][N] row-major (transposed while staging to smem)
template <bool B_KN>
__device__ __forceinline__ void gemm_main(
    const float* __restrict__ Abase, int lda,
    const float* __restrict__ Bbase, int ldb,
    int ktiles,
    uint32_t (*As)[20], uint32_t (*Bs)[20],
    float c[2][8][4], int tid)
{
    const int lane = tid & 31, warp = tid >> 5;
    const int gid = lane >> 2, tig = lane & 3;
    const int wm = warp & 3, wn = warp >> 2;

    for (int kt = 0; kt < ktiles; kt++) {
        const int k0 = kt * 16;
#pragma unroll
        for (int i = 0; i < 2; i++) {
            int t = tid + 256 * i;
            int row = t >> 2, c4 = (t & 3) << 2;
            float4 v = __ldg(reinterpret_cast<const float4*>(
                Abase + (size_t)row * lda + k0 + c4));
            As[row][c4 + 0] = f2tf32(v.x);
            As[row][c4 + 1] = f2tf32(v.y);
            As[row][c4 + 2] = f2tf32(v.z);
            As[row][c4 + 3] = f2tf32(v.w);
        }
        if (B_KN) {
#pragma unroll
            for (int i = 0; i < 2; i++) {
                int t = tid + 256 * i;
                int k = t >> 5, c4 = (t & 31) << 2;
                float4 v = __ldg(reinterpret_cast<const float4*>(
                    Bbase + (size_t)(k0 + k) * ldb + c4));
                Bs[c4 + 0][k] = f2tf32(v.x);
                Bs[c4 + 1][k] = f2tf32(v.y);
                Bs[c4 + 2][k] = f2tf32(v.z);
                Bs[c4 + 3][k] = f2tf32(v.w);
            }
        } else {
#pragma unroll
            for (int i = 0; i < 2; i++) {
                int t = tid + 256 * i;
                int row = t >> 2, c4 = (t & 3) << 2;
                float4 v = __ldg(reinterpret_cast<const float4*>(
                    Bbase + (size_t)row * ldb + k0 + c4));
                Bs[row][c4 + 0] = f2tf32(v.x);
                Bs[row][c4 + 1] = f2tf32(v.y);
                Bs[row][c4 + 2] = f2tf32(v.z);
                Bs[row][c4 + 3] = f2tf32(v.w);
            }
        }
        __syncthreads();

#pragma unroll
        for (int kk = 0; kk < 2; kk++) {
            const int kb = kk << 3;
            uint32_t a[2][4];
#pragma unroll
            for (int ms = 0; ms < 2; ms++) {
                int rb = wm * 32 + ms * 16;
                a[ms][0] = As[rb + gid][kb + tig];
                a[ms][1] = As[rb + gid + 8][kb + tig];
                a[ms][2] = As[rb + gid][kb + tig + 4];
                a[ms][3] = As[rb + gid + 8][kb + tig + 4];
            }
            uint32_t b[8][2];
#pragma unroll
            for (int ns = 0; ns < 8; ns++) {
                int nb = wn * 64 + ns * 8;
                b[ns][0] = Bs[nb + gid][kb + tig];
                b[ns][1] = Bs[nb + gid][kb + tig + 4];
            }
#pragma unroll
            for (int ms = 0; ms < 2; ms++)
#pragma unroll
                for (int ns = 0; ns < 8; ns++)
                    mma_tf32(c[ms][ns], a[ms], b[ns]);
        }
        __syncthreads();
    }
}

// ---------------- K1: QKV projection (stores tf32-rounded) ----------------
__global__ void __launch_bounds__(256, 2) k_qkv(
    const float* __restrict__ x, const float* __restrict__ Wqkv,
    const float* __restrict__ bqkv)
{
    __shared__ uint32_t As[128][20];
    __shared__ uint32_t Bs[128][20];
    const int n = blockIdx.z;
    const int m0 = blockIdx.y * 128;
    const int p0 = blockIdx.x * 128;
    const float* Abase = Wqkv + (size_t)m0 * C_IN;               // [M][K]
    const float* Bbase = x + (size_t)n * C_IN * HW + p0;         // [K][N]
    float c[2][8][4] = {};
    gemm_main<true>(Abase, C_IN, Bbase, HW, C_IN / 16, As, Bs, c, threadIdx.x);

    const int lane = threadIdx.x & 31, warp = threadIdx.x >> 5;
    const int gid = lane >> 2, tig = lane & 3, wm = warp & 3, wn = warp >> 2;
    float* Cb = g_qkv + (size_t)n * OC * HW;
#pragma unroll
    for (int ms = 0; ms < 2; ms++) {
        const int r0 = m0 + wm * 32 + ms * 16 + gid;
        const float b0 = bqkv[r0], b1 = bqkv[r0 + 8];
#pragma unroll
        for (int ns = 0; ns < 8; ns++) {
            const int col = p0 + wn * 64 + ns * 8 + 2 * tig;
            *(float2*)(Cb + (size_t)r0 * HW + col) =
                make_float2(round_tf32(c[ms][ns][0] + b0), round_tf32(c[ms][ns][1] + b0));
            *(float2*)(Cb + (size_t)(r0 + 8) * HW + col) =
                make_float2(round_tf32(c[ms][ns][2] + b1), round_tf32(c[ms][ns][3] + b1));
        }
    }
}

// ---------------- K2: S' = fp16(exp(Q K^T / 64)), column partial sums -----
__global__ void __launch_bounds__(256, 2) k_scores()
{
    __shared__ float As[2][128][20];
    __shared__ float Bs[2][128][20];
    const int n = blockIdx.z;
    const int i0 = blockIdx.y * 128;
    const int j0 = blockIdx.x * 128;
    const float* qb = g_qkv + (size_t)n * OC * HW;
    const float* Abase = qb + (size_t)i0 * 384;          // Q rows   [M][K] ld 384
    const float* Bbase = qb + (size_t)j0 * 384 + 128;    // K rows   [N][K] ld 384
    float c[2][8][4] = {};
    gemm_async(Abase, 384, Bbase, 384, 128 / 16, As, Bs, c, threadIdx.x);

    const int lane = threadIdx.x & 31, warp = threadIdx.x >> 5;
    const int gid = lane >> 2, tig = lane & 3, wm = warp & 3, wn = warp >> 2;
    __half* Sb = g_S + (size_t)n * HW * HW;
    const float scale = 0.015625f;  // 1/sqrt(4096)
    float csum[8][2];
#pragma unroll
    for (int ns = 0; ns < 8; ns++) { csum[ns][0] = 0.f; csum[ns][1] = 0.f; }

#pragma unroll
    for (int ms = 0; ms < 2; ms++) {
        const int r0 = i0 + wm * 32 + ms * 16 + gid;
#pragma unroll
        for (int ns = 0; ns < 8; ns++) {
            const int col = j0 + wn * 64 + ns * 8 + 2 * tig;
            // round exp to fp16 HERE; colsum adds the ROUNDED values so the
            // normalization matches the stored matrix exactly.
            __half h0 = __float2half_rn(fexp(c[ms][ns][0] * scale));
            __half h1 = __float2half_rn(fexp(c[ms][ns][1] * scale));
            __half h2 = __float2half_rn(fexp(c[ms][ns][2] * scale));
            __half h3 = __float2half_rn(fexp(c[ms][ns][3] * scale));
            *(__half2*)(Sb + (size_t)r0 * HW + col)       = __halves2half2(h0, h1);
            *(__half2*)(Sb + (size_t)(r0 + 8) * HW + col) = __halves2half2(h2, h3);
            csum[ns][0] += __half2float(h0) + __half2float(h2);
            csum[ns][1] += __half2float(h1) + __half2float(h3);
        }
    }
    // deterministic column reduction: shfl across row-groups, smem across warps
    float* part = (float*)As;  // smem free after gemm's final sync
#pragma unroll
    for (int ns = 0; ns < 8; ns++) {
#pragma unroll
        for (int jj = 0; jj < 2; jj++) {
            float v = csum[ns][jj];
            v += __shfl_xor_sync(0xffffffffu, v, 4);
            v += __shfl_xor_sync(0xffffffffu, v, 8);
            v += __shfl_xor_sync(0xffffffffu, v, 16);
            if (gid == 0)
                part[wm * 128 + wn * 64 + ns * 8 + 2 * tig + jj] = v;
        }
    }
    __syncthreads();
    const int t = threadIdx.x;
    if (t < 128) {
        float s = part[t] + part[128 + t] + part[256 + t] + part[384 + t];
        g_colpart[((size_t)n * 32 + blockIdx.y) * HW + j0 + t] = s;
    }
}

// ---------------- K2b: reduce column partials -> colsum -------------------
__global__ void k_colreduce()
{
    const int idx = blockIdx.x * 256 + threadIdx.x;   // over N*HW = 16384
    const int n = idx >> 12;
    const int j = idx & 4095;
    float s = 0.f;
#pragma unroll
    for (int b = 0; b < 32; b++)
        s += g_colpart[((size_t)n * 32 + b) * HW + j];
    g_colsum[idx] = s;
}

// ---------------- K3: VsT[d][j] = fp16(256 * V[j,d] / colsum[j]) ----------
__global__ void k_vscale()
{
    __shared__ float t[32][33];
    const int n = blockIdx.z;
    const int j0 = blockIdx.x * 32;
    const int d0 = blockIdx.y * 32;
    const int tx = threadIdx.x, ty = threadIdx.y;
    const float* qb = g_qkv + (size_t)n * OC * HW;
    t[ty][tx] = qb[(size_t)(j0 + ty) * 384 + 256 + d0 + tx];
    __syncthreads();
    const int j = j0 + tx;
    g_VsT[((size_t)n * E_DIM + d0 + ty) * HW + j] =
        __float2half_rn(t[tx][ty] * (VS_SCALE / g_colsum[n * HW + j]));
}

// ---------------- K4: O_partial = S' @ VsT^T (fp16 MMA, split-K) ----------
__global__ void __launch_bounds__(256, 2) k_pv()
{
    __shared__ __half As[2][128][40];
    __shared__ __half Bs[2][128][40];
    const int n = blockIdx.z;
    const int i0 = blockIdx.y * 128;
    const int split = blockIdx.x;
    const int jbase = split * (HW / KSPLIT);
    const __half* Abase = g_S + (size_t)n * HW * HW + (size_t)i0 * HW + jbase;
    const __half* Bbase = g_VsT + (size_t)n * E_DIM * HW + jbase;
    float c[2][8][4] = {};
    gemm_async_f16(Abase, HW, Bbase, HW, (HW / KSPLIT) / 32, As, Bs, c, threadIdx.x);

    const int lane = threadIdx.x & 31, warp = threadIdx.x >> 5;
    const int gid = lane >> 2, tig = lane & 3, wm = warp & 3, wn = warp >> 2;
    float* Ob = g_Opart + ((size_t)split * N_BATCH + n) * HW * E_DIM;
#pragma unroll
    for (int ms = 0; ms < 2; ms++) {
        const int r0 = i0 + wm * 32 + ms * 16 + gid;
#pragma unroll
        for (int ns = 0; ns < 8; ns++) {
            const int col = wn * 64 + ns * 8 + 2 * tig;
            *(float2*)(Ob + (size_t)r0 * E_DIM + col) =
                make_float2(c[ms][ns][0] * VS_INV, c[ms][ns][1] * VS_INV);
            *(float2*)(Ob + (size_t)(r0 + 8) * E_DIM + col) =
                make_float2(c[ms][ns][2] * VS_INV, c[ms][ns][3] * VS_INV);
        }
    }
}

// ---------------- K5: output projection + split-K reduce ------------------
// y[n,c,p] = sum_e Wout[c,e] * (Opart0+Opart1)[n][e*4096 + p] + bout[c]
__global__ void __launch_bounds__(256, 2) k_proj(
    float* __restrict__ out, const float* __restrict__ Wout,
    const float* __restrict__ bout)
{
    __shared__ uint32_t As[128][20];
    __shared__ uint32_t Bs[128][20];
    const int n = blockIdx.z;
    const int c0 = blockIdx.y * 128;
    const int p0 = blockIdx.x * 128;
    const int tid = threadIdx.x;
    const float* Abase = Wout + (size_t)c0 * E_DIM;                               // [M][K] ld 128
    const float* B0 = g_Opart + ((size_t)0 * N_BATCH + n) * HW * E_DIM + p0;      // [K=128][N] ld 4096
    const float* B1 = g_Opart + ((size_t)1 * N_BATCH + n) * HW * E_DIM + p0;

    const int lane = tid & 31, warp = tid >> 5;
    const int gid = lane >> 2, tig = lane & 3;
    const int wm = warp & 3, wn = warp >> 2;
    float c[2][8][4] = {};

    for (int kt = 0; kt < E_DIM / 16; kt++) {
        const int k0 = kt * 16;
#pragma unroll
        for (int i = 0; i < 2; i++) {
            int t = tid + 256 * i;
            int row = t >> 2, c4 = (t & 3) << 2;
            float4 v = __ldg(reinterpret_cast<const float4*>(
                Abase + (size_t)row * E_DIM + k0 + c4));
            As[row][c4 + 0] = f2tf32(v.x);
            As[row][c4 + 1] = f2tf32(v.y);
            As[row][c4 + 2] = f2tf32(v.z);
            As[row][c4 + 3] = f2tf32(v.w);
        }
#pragma unroll
        for (int i = 0; i < 2; i++) {
            int t = tid + 256 * i;
            int k = t >> 5, c4 = (t & 31) << 2;
            size_t off = (size_t)(k0 + k) * HW + c4;
            float4 v0 = __ldg(reinterpret_cast<const float4*>(B0 + off));
            float4 v1 = __ldg(reinterpret_cast<const float4*>(B1 + off));
            Bs[c4 + 0][k] = f2tf32(v0.x + v1.x);
            Bs[c4 + 1][k] = f2tf32(v0.y + v1.y);
            Bs[c4 + 2][k] = f2tf32(v0.z + v1.z);
            Bs[c4 + 3][k] = f2tf32(v0.w + v1.w);
        }
        __syncthreads();

#pragma unroll
        for (int kk = 0; kk < 2; kk++) {
            const int kb = kk << 3;
            uint32_t a[2][4];
#pragma unroll
            for (int ms = 0; ms < 2; ms++) {
                int rb = wm * 32 + ms * 16;
                a[ms][0] = As[rb + gid][kb + tig];
                a[ms][1] = As[rb + gid + 8][kb + tig];
                a[ms][2] = As[rb + gid][kb + tig + 4];
                a[ms][3] = As[rb + gid + 8][kb + tig + 4];
            }
            uint32_t b[8][2];
#pragma unroll
            for (int ns = 0; ns < 8; ns++) {
                int nb = wn * 64 + ns * 8;
                b[ns][0] = Bs[nb + gid][kb + tig];
                b[ns][1] = Bs[nb + gid][kb + tig + 4];
            }
#pragma unroll
            for (int ms = 0; ms < 2; ms++)
#pragma unroll
                for (int ns = 0; ns < 8; ns++)
                    mma_tf32(c[ms][ns], a[ms], b[ns]);
        }
        __syncthreads();
    }

    float* Yb = out + (size_t)n * C_IN * HW;
#pragma unroll
    for (int ms = 0; ms < 2; ms++) {
        const int r0 = c0 + wm * 32 + ms * 16 + gid;
        const float b0 = bout[r0], b1 = bout[r0 + 8];
#pragma unroll
        for (int ns = 0; ns < 8; ns++) {
            const int col = p0 + wn * 64 + ns * 8 + 2 * tig;
            *(float2*)(Yb + (size_t)r0 * HW + col) =
                make_float2(c[ms][ns][0] + b0, c[ms][ns][1] + b0);
            *(float2*)(Yb + (size_t)(r0 + 8) * HW + col) =
                make_float2(c[ms][ns][2] + b1, c[ms][ns][3] + b1);
        }
    }
}

// ---------------- launch ---------------------------------------------------
extern "C" void kernel_launch(void* const* d_in, const int* in_sizes, int n_in,
                              void* d_out, int out_size)
{
    (void)in_sizes; (void)n_in; (void)out_size;
    const float* x    = (const float*)d_in[0];
    const float* Wqkv = (const float*)d_in[1];
    const float* bqkv = (const float*)d_in[2];
    const float* Wout = (const float*)d_in[3];
    const float* bout = (const float*)d_in[4];
    float* out = (float*)d_out;

    dim3 blk(256);
    k_qkv<<<dim3(HW / 128, OC / 128, N_BATCH), blk>>>(x, Wqkv, bqkv);
    k_scores<<<dim3(HW / 128, HW / 128, N_BATCH), blk>>>();
    k_colreduce<<<(N_BATCH * HW) / 256, 256>>>();
    k_vscale<<<dim3(HW / 32, E_DIM / 32, N_BATCH), dim3(32, 32)>>>();
    k_pv<<<dim3(KSPLIT, HW / 128, N_BATCH), blk>>>();
    k_proj<<<dim3(HW / 128, C_IN / 128, N_BATCH), blk>>>(out, Wout, bout);
}

// round 7
// speedup vs baseline: 1.9858x; 1.2257x over previous
#include <cuda_runtime.h>
#include <cuda_fp16.h>
#include <cstdint>
#include <cstddef>

#define N_BATCH 4
#define C_IN    256
#define HW      4096
#define E_DIM   128
#define OC      384   // 3*E
#define KSPLIT  2
#define VS_SCALE 256.0f
#define VS_INV   0.00390625f

// ---------------- scratch (static device globals; no runtime allocation) ----------------
__device__ __half g_qkv[(size_t)N_BATCH * OC * HW];          //  12.6 MB (n,o,p) flat, fp16
__device__ __half g_S[(size_t)N_BATCH * HW * HW];            // 134.2 MB exp(scores), fp16
__device__ float  g_colpart[(size_t)N_BATCH * 32 * HW];      //   2.1 MB per-i-block column partials
__device__ float  g_colsum[(size_t)N_BATCH * HW];            //  64 KB
__device__ __half g_VsT[(size_t)N_BATCH * E_DIM * HW];       //   4.2 MB (n,d,j) = 256*V^T/colsum, fp16
__device__ float  g_Opart[(size_t)KSPLIT * N_BATCH * HW * E_DIM]; // 16.8 MB split-K partials

// ---------------- helpers ----------------
__device__ __forceinline__ uint32_t f2tf32(float x) {
    uint32_t r;
    asm("cvt.rna.tf32.f32 %0, %1;" : "=r"(r) : "f"(x));
    return r;
}

// fast exp for |x| <~ 2 : ~1e-7 relative error, pure FMA/ALU (avoids MUFU throughput wall)
__device__ __forceinline__ float fexp(float x) {
    float t = x * 1.4426950408889634f;
    int   ri = __float2int_rn(t);
    float f = t - (float)ri;
    float u = f * 0.6931471805599453f;
    float p = 1.3888889e-3f;
    p = fmaf(p, u, 8.3333333e-3f);
    p = fmaf(p, u, 4.1666667e-2f);
    p = fmaf(p, u, 1.6666667e-1f);
    p = fmaf(p, u, 0.5f);
    p = fmaf(p, u, 1.0f);
    p = fmaf(p, u, 1.0f);
    return p * __int_as_float((ri + 127) << 23);
}

__device__ __forceinline__ void mma_tf32(float c[4],
                                         const uint32_t a[4],
                                         const uint32_t b[2]) {
    asm volatile(
        "mma.sync.aligned.m16n8k8.row.col.f32.tf32.tf32.f32 "
        "{%0,%1,%2,%3}, {%4,%5,%6,%7}, {%8,%9}, {%0,%1,%2,%3};"
        : "+f"(c[0]), "+f"(c[1]), "+f"(c[2]), "+f"(c[3])
        : "r"(a[0]), "r"(a[1]), "r"(a[2]), "r"(a[3]), "r"(b[0]), "r"(b[1]));
}
__device__ __forceinline__ void mma_f16(float c[4],
                                        const uint32_t a[4],
                                        const uint32_t b[2]) {
    asm volatile(
        "mma.sync.aligned.m16n8k16.row.col.f32.f16.f16.f32 "
        "{%0,%1,%2,%3}, {%4,%5,%6,%7}, {%8,%9}, {%0,%1,%2,%3};"
        : "+f"(c[0]), "+f"(c[1]), "+f"(c[2]), "+f"(c[3])
        : "r"(a[0]), "r"(a[1]), "r"(a[2]), "r"(a[3]), "r"(b[0]), "r"(b[1]));
}

// cp.async 16B helpers
__device__ __forceinline__ void cp16(void* smem_dst, const void* gsrc) {
    uint32_t s = (uint32_t)__cvta_generic_to_shared(smem_dst);
    asm volatile("cp.async.cg.shared.global [%0], [%1], 16;\n" :: "r"(s), "l"(gsrc));
}
__device__ __forceinline__ void cp_commit() {
    asm volatile("cp.async.commit_group;\n");
}
template <int N>
__device__ __forceinline__ void cp_wait() {
    asm volatile("cp.async.wait_group %0;\n" :: "n"(N));
}

// ================= async double-buffered fp16 GEMM core ====================
// C[128x128] fp32 accum, A/B fp16 [row][k] global, k-tile 32.
// 256 threads = 8 warps 4(M)x2(N), warp tile 32x64.
// Smem row stride 40 halfs (80B): 16B-aligned cp.async dsts, conflict-free frags.
__device__ __forceinline__ void gemm_async_f16(
    const __half* __restrict__ Abase, int lda,
    const __half* __restrict__ Bbase, int ldb,
    int ktiles,
    __half (*As)[128][40], __half (*Bs)[128][40],
    float c[2][8][4], int tid)
{
    const int lane = tid & 31, warp = tid >> 5;
    const int gid = lane >> 2, tig = lane & 3;
    const int wm = warp & 3, wn = warp >> 2;
    const int r0 = tid >> 2, h8 = (tid & 3) << 3;  // 8 halfs = 16 B per cp

    auto issue = [&](int kt, int buf) {
        const int k0 = kt * 32;
        cp16(&As[buf][r0][h8],      Abase + (size_t)r0 * lda + k0 + h8);
        cp16(&As[buf][r0 + 64][h8], Abase + (size_t)(r0 + 64) * lda + k0 + h8);
        cp16(&Bs[buf][r0][h8],      Bbase + (size_t)r0 * ldb + k0 + h8);
        cp16(&Bs[buf][r0 + 64][h8], Bbase + (size_t)(r0 + 64) * ldb + k0 + h8);
        cp_commit();
    };

    issue(0, 0);
    for (int kt = 0; kt < ktiles; kt++) {
        const int buf = kt & 1;
        if (kt + 1 < ktiles) { issue(kt + 1, (kt + 1) & 1); cp_wait<1>(); }
        else                 { cp_wait<0>(); }
        __syncthreads();

#pragma unroll
        for (int kk = 0; kk < 2; kk++) {
            const int kb = kk << 4;
            uint32_t a[2][4];
#pragma unroll
            for (int ms = 0; ms < 2; ms++) {
                int rb = wm * 32 + ms * 16;
                a[ms][0] = *(const uint32_t*)&As[buf][rb + gid][kb + 2 * tig];
                a[ms][1] = *(const uint32_t*)&As[buf][rb + gid + 8][kb + 2 * tig];
                a[ms][2] = *(const uint32_t*)&As[buf][rb + gid][kb + 2 * tig + 8];
                a[ms][3] = *(const uint32_t*)&As[buf][rb + gid + 8][kb + 2 * tig + 8];
            }
            uint32_t b[8][2];
#pragma unroll
            for (int ns = 0; ns < 8; ns++) {
                int nb = wn * 64 + ns * 8;
                b[ns][0] = *(const uint32_t*)&Bs[buf][nb + gid][kb + 2 * tig];
                b[ns][1] = *(const uint32_t*)&Bs[buf][nb + gid][kb + 2 * tig + 8];
            }
#pragma unroll
            for (int ms = 0; ms < 2; ms++)
#pragma unroll
                for (int ns = 0; ns < 8; ns++)
                    mma_f16(c[ms][ns], a[ms], b[ns]);
        }
        __syncthreads();
    }
}

// ================= LDG+cvt tf32 GEMM core (external fp32 inputs) ==========
// B_KN=true : global B is [K][N] row-major (transposed while staging to smem)
template <bool B_KN>
__device__ __forceinline__ void gemm_main(
    const float* __restrict__ Abase, int lda,
    const float* __restrict__ Bbase, int ldb,
    int ktiles,
    uint32_t (*As)[20], uint32_t (*Bs)[20],
    float c[2][8][4], int tid)
{
    const int lane = tid & 31, warp = tid >> 5;
    const int gid = lane >> 2, tig = lane & 3;
    const int wm = warp & 3, wn = warp >> 2;

    for (int kt = 0; kt < ktiles; kt++) {
        const int k0 = kt * 16;
#pragma unroll
        for (int i = 0; i < 2; i++) {
            int t = tid + 256 * i;
            int row = t >> 2, c4 = (t & 3) << 2;
            float4 v = __ldg(reinterpret_cast<const float4*>(
                Abase + (size_t)row * lda + k0 + c4));
            As[row][c4 + 0] = f2tf32(v.x);
            As[row][c4 + 1] = f2tf32(v.y);
            As[row][c4 + 2] = f2tf32(v.z);
            As[row][c4 + 3] = f2tf32(v.w);
        }
        if (B_KN) {
#pragma unroll
            for (int i = 0; i < 2; i++) {
                int t = tid + 256 * i;
                int k = t >> 5, c4 = (t & 31) << 2;
                float4 v = __ldg(reinterpret_cast<const float4*>(
                    Bbase + (size_t)(k0 + k) * ldb + c4));
                Bs[c4 + 0][k] = f2tf32(v.x);
                Bs[c4 + 1][k] = f2tf32(v.y);
                Bs[c4 + 2][k] = f2tf32(v.z);
                Bs[c4 + 3][k] = f2tf32(v.w);
            }
        } else {
#pragma unroll
            for (int i = 0; i < 2; i++) {
                int t = tid + 256 * i;
                int row = t >> 2, c4 = (t & 3) << 2;
                float4 v = __ldg(reinterpret_cast<const float4*>(
                    Bbase + (size_t)row * ldb + k0 + c4));
                Bs[row][c4 + 0] = f2tf32(v.x);
                Bs[row][c4 + 1] = f2tf32(v.y);
                Bs[row][c4 + 2] = f2tf32(v.z);
                Bs[row][c4 + 3] = f2tf32(v.w);
            }
        }
        __syncthreads();

#pragma unroll
        for (int kk = 0; kk < 2; kk++) {
            const int kb = kk << 3;
            uint32_t a[2][4];
#pragma unroll
            for (int ms = 0; ms < 2; ms++) {
                int rb = wm * 32 + ms * 16;
                a[ms][0] = As[rb + gid][kb + tig];
                a[ms][1] = As[rb + gid + 8][kb + tig];
                a[ms][2] = As[rb + gid][kb + tig + 4];
                a[ms][3] = As[rb + gid + 8][kb + tig + 4];
            }
            uint32_t b[8][2];
#pragma unroll
            for (int ns = 0; ns < 8; ns++) {
                int nb = wn * 64 + ns * 8;
                b[ns][0] = Bs[nb + gid][kb + tig];
                b[ns][1] = Bs[nb + gid][kb + tig + 4];
            }
#pragma unroll
            for (int ms = 0; ms < 2; ms++)
#pragma unroll
                for (int ns = 0; ns < 8; ns++)
                    mma_tf32(c[ms][ns], a[ms], b[ns]);
        }
        __syncthreads();
    }
}

// ---------------- K1: QKV projection (stores fp16) ------------------------
// qkv[n,o,p] = fp16( sum_c Wqkv[o,c] * x[n,c,p] + bqkv[o] )
__global__ void __launch_bounds__(256, 2) k_qkv(
    const float* __restrict__ x, const float* __restrict__ Wqkv,
    const float* __restrict__ bqkv)
{
    __shared__ uint32_t As[128][20];
    __shared__ uint32_t Bs[128][20];
    const int n = blockIdx.z;
    const int m0 = blockIdx.y * 128;
    const int p0 = blockIdx.x * 128;
    const float* Abase = Wqkv + (size_t)m0 * C_IN;               // [M][K]
    const float* Bbase = x + (size_t)n * C_IN * HW + p0;         // [K][N]
    float c[2][8][4] = {};
    gemm_main<true>(Abase, C_IN, Bbase, HW, C_IN / 16, As, Bs, c, threadIdx.x);

    const int lane = threadIdx.x & 31, warp = threadIdx.x >> 5;
    const int gid = lane >> 2, tig = lane & 3, wm = warp & 3, wn = warp >> 2;
    __half* Cb = g_qkv + (size_t)n * OC * HW;
#pragma unroll
    for (int ms = 0; ms < 2; ms++) {
        const int r0 = m0 + wm * 32 + ms * 16 + gid;
        const float b0 = bqkv[r0], b1 = bqkv[r0 + 8];
#pragma unroll
        for (int ns = 0; ns < 8; ns++) {
            const int col = p0 + wn * 64 + ns * 8 + 2 * tig;
            *(__half2*)(Cb + (size_t)r0 * HW + col) =
                __halves2half2(__float2half_rn(c[ms][ns][0] + b0),
                               __float2half_rn(c[ms][ns][1] + b0));
            *(__half2*)(Cb + (size_t)(r0 + 8) * HW + col) =
                __halves2half2(__float2half_rn(c[ms][ns][2] + b1),
                               __float2half_rn(c[ms][ns][3] + b1));
        }
    }
}

// ---------------- K2: S' = fp16(exp(Q K^T / 64)), column partial sums -----
// Faithful reshape: Q[i,k] = qkv_flat[i*384 + k], K[j,k] = qkv_flat[j*384 + 128 + k]
__global__ void __launch_bounds__(256, 2) k_scores()
{
    __shared__ __half As[2][128][40];
    __shared__ __half Bs[2][128][40];
    const int n = blockIdx.z;
    const int i0 = blockIdx.y * 128;
    const int j0 = blockIdx.x * 128;
    const __half* qb = g_qkv + (size_t)n * OC * HW;
    const __half* Abase = qb + (size_t)i0 * 384;          // Q rows  [M][K] ld 384
    const __half* Bbase = qb + (size_t)j0 * 384 + 128;    // K rows  [N][K] ld 384
    float c[2][8][4] = {};
    gemm_async_f16(Abase, 384, Bbase, 384, 128 / 32, As, Bs, c, threadIdx.x);

    const int lane = threadIdx.x & 31, warp = threadIdx.x >> 5;
    const int gid = lane >> 2, tig = lane & 3, wm = warp & 3, wn = warp >> 2;
    __half* Sb = g_S + (size_t)n * HW * HW;
    const float scale = 0.015625f;  // 1/sqrt(4096)
    float csum[8][2];
#pragma unroll
    for (int ns = 0; ns < 8; ns++) { csum[ns][0] = 0.f; csum[ns][1] = 0.f; }

#pragma unroll
    for (int ms = 0; ms < 2; ms++) {
        const int r0 = i0 + wm * 32 + ms * 16 + gid;
#pragma unroll
        for (int ns = 0; ns < 8; ns++) {
            const int col = j0 + wn * 64 + ns * 8 + 2 * tig;
            // round exp to fp16 HERE; colsum adds the ROUNDED values so the
            // normalization matches the stored matrix exactly.
            __half h0 = __float2half_rn(fexp(c[ms][ns][0] * scale));
            __half h1 = __float2half_rn(fexp(c[ms][ns][1] * scale));
            __half h2 = __float2half_rn(fexp(c[ms][ns][2] * scale));
            __half h3 = __float2half_rn(fexp(c[ms][ns][3] * scale));
            *(__half2*)(Sb + (size_t)r0 * HW + col)       = __halves2half2(h0, h1);
            *(__half2*)(Sb + (size_t)(r0 + 8) * HW + col) = __halves2half2(h2, h3);
            csum[ns][0] += __half2float(h0) + __half2float(h2);
            csum[ns][1] += __half2float(h1) + __half2float(h3);
        }
    }
    // deterministic column reduction: shfl across row-groups, smem across warps
    float* part = (float*)As;  // smem free after gemm's final sync (20 KB >= 2 KB)
#pragma unroll
    for (int ns = 0; ns < 8; ns++) {
#pragma unroll
        for (int jj = 0; jj < 2; jj++) {
            float v = csum[ns][jj];
            v += __shfl_xor_sync(0xffffffffu, v, 4);
            v += __shfl_xor_sync(0xffffffffu, v, 8);
            v += __shfl_xor_sync(0xffffffffu, v, 16);
            if (gid == 0)
                part[wm * 128 + wn * 64 + ns * 8 + 2 * tig + jj] = v;
        }
    }
    __syncthreads();
    const int t = threadIdx.x;
    if (t < 128) {
        float s = part[t] + part[128 + t] + part[256 + t] + part[384 + t];
        g_colpart[((size_t)n * 32 + blockIdx.y) * HW + j0 + t] = s;
    }
}

// ---------------- K2b: reduce column partials -> colsum -------------------
__global__ void k_colreduce()
{
    const int idx = blockIdx.x * 256 + threadIdx.x;   // over N*HW = 16384
    const int n = idx >> 12;
    const int j = idx & 4095;
    float s = 0.f;
#pragma unroll
    for (int b = 0; b < 32; b++)
        s += g_colpart[((size_t)n * 32 + b) * HW + j];
    g_colsum[idx] = s;
}

// ---------------- K3: VsT[d][j] = fp16(256 * V[j,d] / colsum[j]) ----------
__global__ void k_vscale()
{
    __shared__ float t[32][33];
    const int n = blockIdx.z;
    const int j0 = blockIdx.x * 32;
    const int d0 = blockIdx.y * 32;
    const int tx = threadIdx.x, ty = threadIdx.y;
    const __half* qb = g_qkv + (size_t)n * OC * HW;
    t[ty][tx] = __half2float(qb[(size_t)(j0 + ty) * 384 + 256 + d0 + tx]);
    __syncthreads();
    const int j = j0 + tx;
    g_VsT[((size_t)n * E_DIM + d0 + ty) * HW + j] =
        __float2half_rn(t[tx][ty] * (VS_SCALE / g_colsum[n * HW + j]));
}

// ---------------- K4: O_partial = S' @ VsT^T (fp16 MMA, split-K) ----------
__global__ void __launch_bounds__(256, 2) k_pv()
{
    __shared__ __half As[2][128][40];
    __shared__ __half Bs[2][128][40];
    const int n = blockIdx.z;
    const int i0 = blockIdx.y * 128;
    const int split = blockIdx.x;
    const int jbase = split * (HW / KSPLIT);
    const __half* Abase = g_S + (size_t)n * HW * HW + (size_t)i0 * HW + jbase;
    const __half* Bbase = g_VsT + (size_t)n * E_DIM * HW + jbase;
    float c[2][8][4] = {};
    gemm_async_f16(Abase, HW, Bbase, HW, (HW / KSPLIT) / 32, As, Bs, c, threadIdx.x);

    const int lane = threadIdx.x & 31, warp = threadIdx.x >> 5;
    const int gid = lane >> 2, tig = lane & 3, wm = warp & 3, wn = warp >> 2;
    float* Ob = g_Opart + ((size_t)split * N_BATCH + n) * HW * E_DIM;
#pragma unroll
    for (int ms = 0; ms < 2; ms++) {
        const int r0 = i0 + wm * 32 + ms * 16 + gid;
#pragma unroll
        for (int ns = 0; ns < 8; ns++) {
            const int col = wn * 64 + ns * 8 + 2 * tig;
            *(float2*)(Ob + (size_t)r0 * E_DIM + col) =
                make_float2(c[ms][ns][0] * VS_INV, c[ms][ns][1] * VS_INV);
            *(float2*)(Ob + (size_t)(r0 + 8) * E_DIM + col) =
                make_float2(c[ms][ns][2] * VS_INV, c[ms][ns][3] * VS_INV);
        }
    }
}

// ---------------- K5: output projection + split-K reduce ------------------
// y[n,c,p] = sum_e Wout[c,e] * (Opart0+Opart1)[n][e*4096 + p] + bout[c]
__global__ void __launch_bounds__(256, 2) k_proj(
    float* __restrict__ out, const float* __restrict__ Wout,
    const float* __restrict__ bout)
{
    __shared__ uint32_t As[128][20];
    __shared__ uint32_t Bs[128][20];
    const int n = blockIdx.z;
    const int c0 = blockIdx.y * 128;
    const int p0 = blockIdx.x * 128;
    const int tid = threadIdx.x;
    const float* Abase = Wout + (size_t)c0 * E_DIM;                               // [M][K] ld 128
    const float* B0 = g_Opart + ((size_t)0 * N_BATCH + n) * HW * E_DIM + p0;      // [K=128][N] ld 4096
    const float* B1 = g_Opart + ((size_t)1 * N_BATCH + n) * HW * E_DIM + p0;

    const int lane = tid & 31, warp = tid >> 5;
    const int gid = lane >> 2, tig = lane & 3;
    const int wm = warp & 3, wn = warp >> 2;
    float c[2][8][4] = {};

    for (int kt = 0; kt < E_DIM / 16; kt++) {
        const int k0 = kt * 16;
#pragma unroll
        for (int i = 0; i < 2; i++) {
            int t = tid + 256 * i;
            int row = t >> 2, c4 = (t & 3) << 2;
            float4 v = __ldg(reinterpret_cast<const float4*>(
                Abase + (size_t)row * E_DIM + k0 + c4));
            As[row][c4 + 0] = f2tf32(v.x);
            As[row][c4 + 1] = f2tf32(v.y);
            As[row][c4 + 2] = f2tf32(v.z);
            As[row][c4 + 3] = f2tf32(v.w);
        }
#pragma unroll
        for (int i = 0; i < 2; i++) {
            int t = tid + 256 * i;
            int k = t >> 5, c4 = (t & 31) << 2;
            size_t off = (size_t)(k0 + k) * HW + c4;
            float4 v0 = __ldg(reinterpret_cast<const float4*>(B0 + off));
            float4 v1 = __ldg(reinterpret_cast<const float4*>(B1 + off));
            Bs[c4 + 0][k] = f2tf32(v0.x + v1.x);
            Bs[c4 + 1][k] = f2tf32(v0.y + v1.y);
            Bs[c4 + 2][k] = f2tf32(v0.z + v1.z);
            Bs[c4 + 3][k] = f2tf32(v0.w + v1.w);
        }
        __syncthreads();

#pragma unroll
        for (int kk = 0; kk < 2; kk++) {
            const int kb = kk << 3;
            uint32_t a[2][4];
#pragma unroll
            for (int ms = 0; ms < 2; ms++) {
                int rb = wm * 32 + ms * 16;
                a[ms][0] = As[rb + gid][kb + tig];
                a[ms][1] = As[rb + gid + 8][kb + tig];
                a[ms][2] = As[rb + gid][kb + tig + 4];
                a[ms][3] = As[rb + gid + 8][kb + tig + 4];
            }
            uint32_t b[8][2];
#pragma unroll
            for (int ns = 0; ns < 8; ns++) {
                int nb = wn * 64 + ns * 8;
                b[ns][0] = Bs[nb + gid][kb + tig];
                b[ns][1] = Bs[nb + gid][kb + tig + 4];
            }
#pragma unroll
            for (int ms = 0; ms < 2; ms++)
#pragma unroll
                for (int ns = 0; ns < 8; ns++)
                    mma_tf32(c[ms][ns], a[ms], b[ns]);
        }
        __syncthreads();
    }

    float* Yb = out + (size_t)n * C_IN * HW;
#pragma unroll
    for (int ms = 0; ms < 2; ms++) {
        const int r0 = c0 + wm * 32 + ms * 16 + gid;
        const float b0 = bout[r0], b1 = bout[r0 + 8];
#pragma unroll
        for (int ns = 0; ns < 8; ns++) {
            const int col = p0 + wn * 64 + ns * 8 + 2 * tig;
            *(float2*)(Yb + (size_t)r0 * HW + col) =
                make_float2(c[ms][ns][0] + b0, c[ms][ns][1] + b0);
            *(float2*)(Yb + (size_t)(r0 + 8) * HW + col) =
                make_float2(c[ms][ns][2] + b1, c[ms][ns][3] + b1);
        }
    }
}

// ---------------- launch ---------------------------------------------------
extern "C" void kernel_launch(void* const* d_in, const int* in_sizes, int n_in,
                              void* d_out, int out_size)
{
    (void)in_sizes; (void)n_in; (void)out_size;
    const float* x    = (const float*)d_in[0];
    const float* Wqkv = (const float*)d_in[1];
    const float* bqkv = (const float*)d_in[2];
    const float* Wout = (const float*)d_in[3];
    const float* bout = (const float*)d_in[4];
    float* out = (float*)d_out;

    dim3 blk(256);
    k_qkv<<<dim3(HW / 128, OC / 128, N_BATCH), blk>>>(x, Wqkv, bqkv);
    k_scores<<<dim3(HW / 128, HW / 128, N_BATCH), blk>>>();
    k_colreduce<<<(N_BATCH * HW) / 256, 256>>>();
    k_vscale<<<dim3(HW / 32, E_DIM / 32, N_BATCH), dim3(32, 32)>>>();
    k_pv<<<dim3(KSPLIT, HW / 128, N_BATCH), blk>>>();
    k_proj<<<dim3(HW / 128, C_IN / 128, N_BATCH), blk>>>(out, Wout, bout);
}

// round 8
// speedup vs baseline: 1.9987x; 1.0065x over previous
#include <cuda_runtime.h>
#include <cuda_fp16.h>
#include <cstdint>
#include <cstddef>

#define N_BATCH 4
#define C_IN    256
#define HW      4096
#define E_DIM   128
#define OC      384   // 3*E
#define KSPLIT  2
#define VS_SCALE 256.0f
#define VS_INV   0.00390625f

// ---------------- scratch (static device globals; no runtime allocation) ----------------
__device__ __half g_qkv[(size_t)N_BATCH * OC * HW];          //  12.6 MB (n,o,p) flat, fp16
__device__ __half g_S[(size_t)N_BATCH * HW * HW];            // 134.2 MB exp(scores), fp16
__device__ float  g_colpart[(size_t)N_BATCH * 32 * HW];      //   2.1 MB per-i-block column partials
__device__ float  g_colsum[(size_t)N_BATCH * HW];            //  64 KB
__device__ __half g_VsT[(size_t)N_BATCH * E_DIM * HW];       //   4.2 MB (n,d,j) = 256*V^T/colsum, fp16
__device__ __half g_Opart[(size_t)KSPLIT * N_BATCH * HW * E_DIM]; // 8.4 MB split-K partials, fp16

// ---------------- helpers ----------------
__device__ __forceinline__ uint32_t f2tf32(float x) {
    uint32_t r;
    asm("cvt.rna.tf32.f32 %0, %1;" : "=r"(r) : "f"(x));
    return r;
}

// fast exp for |x| <~ 2 : ~1e-7 relative error, pure FMA/ALU (avoids MUFU throughput wall)
__device__ __forceinline__ float fexp(float x) {
    float t = x * 1.4426950408889634f;
    int   ri = __float2int_rn(t);
    float f = t - (float)ri;
    float u = f * 0.6931471805599453f;
    float p = 1.3888889e-3f;
    p = fmaf(p, u, 8.3333333e-3f);
    p = fmaf(p, u, 4.1666667e-2f);
    p = fmaf(p, u, 1.6666667e-1f);
    p = fmaf(p, u, 0.5f);
    p = fmaf(p, u, 1.0f);
    p = fmaf(p, u, 1.0f);
    return p * __int_as_float((ri + 127) << 23);
}

__device__ __forceinline__ void mma_tf32(float c[4],
                                         const uint32_t a[4],
                                         const uint32_t b[2]) {
    asm volatile(
        "mma.sync.aligned.m16n8k8.row.col.f32.tf32.tf32.f32 "
        "{%0,%1,%2,%3}, {%4,%5,%6,%7}, {%8,%9}, {%0,%1,%2,%3};"
        : "+f"(c[0]), "+f"(c[1]), "+f"(c[2]), "+f"(c[3])
        : "r"(a[0]), "r"(a[1]), "r"(a[2]), "r"(a[3]), "r"(b[0]), "r"(b[1]));
}
__device__ __forceinline__ void mma_f16(float c[4],
                                        const uint32_t a[4],
                                        const uint32_t b[2]) {
    asm volatile(
        "mma.sync.aligned.m16n8k16.row.col.f32.f16.f16.f32 "
        "{%0,%1,%2,%3}, {%4,%5,%6,%7}, {%8,%9}, {%0,%1,%2,%3};"
        : "+f"(c[0]), "+f"(c[1]), "+f"(c[2]), "+f"(c[3])
        : "r"(a[0]), "r"(a[1]), "r"(a[2]), "r"(a[3]), "r"(b[0]), "r"(b[1]));
}

// ldmatrix x4: four 8x8 b16 fragments in one shared-pipe instruction
__device__ __forceinline__ void ldsm_x4(uint32_t& r0, uint32_t& r1,
                                        uint32_t& r2, uint32_t& r3,
                                        const void* p) {
    uint32_t addr = (uint32_t)__cvta_generic_to_shared(p);
    asm volatile("ldmatrix.sync.aligned.m8n8.x4.shared.b16 {%0,%1,%2,%3}, [%4];\n"
                 : "=r"(r0), "=r"(r1), "=r"(r2), "=r"(r3) : "r"(addr));
}

// cp.async 16B helpers
__device__ __forceinline__ void cp16(void* smem_dst, const void* gsrc) {
    uint32_t s = (uint32_t)__cvta_generic_to_shared(smem_dst);
    asm volatile("cp.async.cg.shared.global [%0], [%1], 16;\n" :: "r"(s), "l"(gsrc));
}
__device__ __forceinline__ void cp_commit() {
    asm volatile("cp.async.commit_group;\n");
}
template <int N>
__device__ __forceinline__ void cp_wait() {
    asm volatile("cp.async.wait_group %0;\n" :: "n"(N));
}

// ================= async double-buffered fp16 GEMM core (ldmatrix) ========
// C[128x128] fp32 accum, A/B fp16 [row][k] global, k-tile 32.
// 256 threads = 8 warps 4(M)x2(N), warp tile 32x64.
// Smem row stride 40 halfs (80B): 16B-aligned cp.async dsts; ldmatrix rows at
// 20-word stride cover all 32 banks conflict-free.
__device__ __forceinline__ void gemm_async_f16(
    const __half* __restrict__ Abase, int lda,
    const __half* __restrict__ Bbase, int ldb,
    int ktiles,
    __half (*As)[128][40], __half (*Bs)[128][40],
    float c[2][8][4], int tid)
{
    const int lane = tid & 31, warp = tid >> 5;
    const int wm = warp & 3, wn = warp >> 2;
    const int r0 = tid >> 2, h8 = (tid & 3) << 3;  // 8 halfs = 16 B per cp
    const int lrow = lane & 15, lcol = (lane >> 4) << 3;  // ldmatrix addressing

    auto issue = [&](int kt, int buf) {
        const int k0 = kt * 32;
        cp16(&As[buf][r0][h8],      Abase + (size_t)r0 * lda + k0 + h8);
        cp16(&As[buf][r0 + 64][h8], Abase + (size_t)(r0 + 64) * lda + k0 + h8);
        cp16(&Bs[buf][r0][h8],      Bbase + (size_t)r0 * ldb + k0 + h8);
        cp16(&Bs[buf][r0 + 64][h8], Bbase + (size_t)(r0 + 64) * ldb + k0 + h8);
        cp_commit();
    };

    issue(0, 0);
    for (int kt = 0; kt < ktiles; kt++) {
        const int buf = kt & 1;
        if (kt + 1 < ktiles) { issue(kt + 1, (kt + 1) & 1); cp_wait<1>(); }
        else                 { cp_wait<0>(); }
        __syncthreads();

#pragma unroll
        for (int kk = 0; kk < 2; kk++) {
            const int kb = kk << 4;
            uint32_t a[2][4];
#pragma unroll
            for (int ms = 0; ms < 2; ms++) {
                int rb = wm * 32 + ms * 16;
                ldsm_x4(a[ms][0], a[ms][1], a[ms][2], a[ms][3],
                        &As[buf][rb + lrow][kb + lcol]);
            }
            uint32_t b[8][2];
#pragma unroll
            for (int g = 0; g < 4; g++) {
                int nb = wn * 64 + g * 16;
                uint32_t m0, m1, m2, m3;
                ldsm_x4(m0, m1, m2, m3, &Bs[buf][nb + lrow][kb + lcol]);
                b[2 * g][0]     = m0; b[2 * g][1]     = m2;
                b[2 * g + 1][0] = m1; b[2 * g + 1][1] = m3;
            }
#pragma unroll
            for (int ms = 0; ms < 2; ms++)
#pragma unroll
                for (int ns = 0; ns < 8; ns++)
                    mma_f16(c[ms][ns], a[ms], b[ns]);
        }
        __syncthreads();
    }
}

// ================= LDG+cvt tf32 GEMM core (external fp32 inputs) ==========
// B_KN=true : global B is [K][N] row-major (transposed while staging to smem)
template <bool B_KN>
__device__ __forceinline__ void gemm_main(
    const float* __restrict__ Abase, int lda,
    const float* __restrict__ Bbase, int ldb,
    int ktiles,
    uint32_t (*As)[20], uint32_t (*Bs)[20],
    float c[2][8][4], int tid)
{
    const int lane = tid & 31, warp = tid >> 5;
    const int gid = lane >> 2, tig = lane & 3;
    const int wm = warp & 3, wn = warp >> 2;

    for (int kt = 0; kt < ktiles; kt++) {
        const int k0 = kt * 16;
#pragma unroll
        for (int i = 0; i < 2; i++) {
            int t = tid + 256 * i;
            int row = t >> 2, c4 = (t & 3) << 2;
            float4 v = __ldg(reinterpret_cast<const float4*>(
                Abase + (size_t)row * lda + k0 + c4));
            As[row][c4 + 0] = f2tf32(v.x);
            As[row][c4 + 1] = f2tf32(v.y);
            As[row][c4 + 2] = f2tf32(v.z);
            As[row][c4 + 3] = f2tf32(v.w);
        }
        if (B_KN) {
#pragma unroll
            for (int i = 0; i < 2; i++) {
                int t = tid + 256 * i;
                int k = t >> 5, c4 = (t & 31) << 2;
                float4 v = __ldg(reinterpret_cast<const float4*>(
                    Bbase + (size_t)(k0 + k) * ldb + c4));
                Bs[c4 + 0][k] = f2tf32(v.x);
                Bs[c4 + 1][k] = f2tf32(v.y);
                Bs[c4 + 2][k] = f2tf32(v.z);
                Bs[c4 + 3][k] = f2tf32(v.w);
            }
        } else {
#pragma unroll
            for (int i = 0; i < 2; i++) {
                int t = tid + 256 * i;
                int row = t >> 2, c4 = (t & 3) << 2;
                float4 v = __ldg(reinterpret_cast<const float4*>(
                    Bbase + (size_t)row * ldb + k0 + c4));
                Bs[row][c4 + 0] = f2tf32(v.x);
                Bs[row][c4 + 1] = f2tf32(v.y);
                Bs[row][c4 + 2] = f2tf32(v.z);
                Bs[row][c4 + 3] = f2tf32(v.w);
            }
        }
        __syncthreads();

#pragma unroll
        for (int kk = 0; kk < 2; kk++) {
            const int kb = kk << 3;
            uint32_t a[2][4];
#pragma unroll
            for (int ms = 0; ms < 2; ms++) {
                int rb = wm * 32 + ms * 16;
                a[ms][0] = As[rb + gid][kb + tig];
                a[ms][1] = As[rb + gid + 8][kb + tig];
                a[ms][2] = As[rb + gid][kb + tig + 4];
                a[ms][3] = As[rb + gid + 8][kb + tig + 4];
            }
            uint32_t b[8][2];
#pragma unroll
            for (int ns = 0; ns < 8; ns++) {
                int nb = wn * 64 + ns * 8;
                b[ns][0] = Bs[nb + gid][kb + tig];
                b[ns][1] = Bs[nb + gid][kb + tig + 4];
            }
#pragma unroll
            for (int ms = 0; ms < 2; ms++)
#pragma unroll
                for (int ns = 0; ns < 8; ns++)
                    mma_tf32(c[ms][ns], a[ms], b[ns]);
        }
        __syncthreads();
    }
}

// ---------------- K1: QKV projection (stores fp16) ------------------------
// qkv[n,o,p] = fp16( sum_c Wqkv[o,c] * x[n,c,p] + bqkv[o] )
__global__ void __launch_bounds__(256, 2) k_qkv(
    const float* __restrict__ x, const float* __restrict__ Wqkv,
    const float* __restrict__ bqkv)
{
    __shared__ uint32_t As[128][20];
    __shared__ uint32_t Bs[128][20];
    const int n = blockIdx.z;
    const int m0 = blockIdx.y * 128;
    const int p0 = blockIdx.x * 128;
    const float* Abase = Wqkv + (size_t)m0 * C_IN;               // [M][K]
    const float* Bbase = x + (size_t)n * C_IN * HW + p0;         // [K][N]
    float c[2][8][4] = {};
    gemm_main<true>(Abase, C_IN, Bbase, HW, C_IN / 16, As, Bs, c, threadIdx.x);

    const int lane = threadIdx.x & 31, warp = threadIdx.x >> 5;
    const int gid = lane >> 2, tig = lane & 3, wm = warp & 3, wn = warp >> 2;
    __half* Cb = g_qkv + (size_t)n * OC * HW;
#pragma unroll
    for (int ms = 0; ms < 2; ms++) {
        const int r0 = m0 + wm * 32 + ms * 16 + gid;
        const float b0 = bqkv[r0], b1 = bqkv[r0 + 8];
#pragma unroll
        for (int ns = 0; ns < 8; ns++) {
            const int col = p0 + wn * 64 + ns * 8 + 2 * tig;
            *(__half2*)(Cb + (size_t)r0 * HW + col) =
                __halves2half2(__float2half_rn(c[ms][ns][0] + b0),
                               __float2half_rn(c[ms][ns][1] + b0));
            *(__half2*)(Cb + (size_t)(r0 + 8) * HW + col) =
                __halves2half2(__float2half_rn(c[ms][ns][2] + b1),
                               __float2half_rn(c[ms][ns][3] + b1));
        }
    }
}

// ---------------- K2: S' = fp16(exp(Q K^T / 64)), column partial sums -----
// Faithful reshape: Q[i,k] = qkv_flat[i*384 + k], K[j,k] = qkv_flat[j*384 + 128 + k]
__global__ void __launch_bounds__(256, 2) k_scores()
{
    __shared__ __half As[2][128][40];
    __shared__ __half Bs[2][128][40];
    const int n = blockIdx.z;
    const int i0 = blockIdx.y * 128;
    const int j0 = blockIdx.x * 128;
    const __half* qb = g_qkv + (size_t)n * OC * HW;
    const __half* Abase = qb + (size_t)i0 * 384;          // Q rows  [M][K] ld 384
    const __half* Bbase = qb + (size_t)j0 * 384 + 128;    // K rows  [N][K] ld 384
    float c[2][8][4] = {};
    gemm_async_f16(Abase, 384, Bbase, 384, 128 / 32, As, Bs, c, threadIdx.x);

    const int lane = threadIdx.x & 31, warp = threadIdx.x >> 5;
    const int gid = lane >> 2, tig = lane & 3, wm = warp & 3, wn = warp >> 2;
    __half* Sb = g_S + (size_t)n * HW * HW;
    const float scale = 0.015625f;  // 1/sqrt(4096)
    float csum[8][2];
#pragma unroll
    for (int ns = 0; ns < 8; ns++) { csum[ns][0] = 0.f; csum[ns][1] = 0.f; }

#pragma unroll
    for (int ms = 0; ms < 2; ms++) {
        const int r0 = i0 + wm * 32 + ms * 16 + gid;
#pragma unroll
        for (int ns = 0; ns < 8; ns++) {
            const int col = j0 + wn * 64 + ns * 8 + 2 * tig;
            // round exp to fp16 HERE; colsum adds the ROUNDED values so the
            // normalization matches the stored matrix exactly.
            __half h0 = __float2half_rn(fexp(c[ms][ns][0] * scale));
            __half h1 = __float2half_rn(fexp(c[ms][ns][1] * scale));
            __half h2 = __float2half_rn(fexp(c[ms][ns][2] * scale));
            __half h3 = __float2half_rn(fexp(c[ms][ns][3] * scale));
            *(__half2*)(Sb + (size_t)r0 * HW + col)       = __halves2half2(h0, h1);
            *(__half2*)(Sb + (size_t)(r0 + 8) * HW + col) = __halves2half2(h2, h3);
            csum[ns][0] += __half2float(h0) + __half2float(h2);
            csum[ns][1] += __half2float(h1) + __half2float(h3);
        }
    }
    // deterministic column reduction: shfl across row-groups, smem across warps
    float* part = (float*)As;  // smem free after gemm's final sync (20 KB >= 2 KB)
#pragma unroll
    for (int ns = 0; ns < 8; ns++) {
#pragma unroll
        for (int jj = 0; jj < 2; jj++) {
            float v = csum[ns][jj];
            v += __shfl_xor_sync(0xffffffffu, v, 4);
            v += __shfl_xor_sync(0xffffffffu, v, 8);
            v += __shfl_xor_sync(0xffffffffu, v, 16);
            if (gid == 0)
                part[wm * 128 + wn * 64 + ns * 8 + 2 * tig + jj] = v;
        }
    }
    __syncthreads();
    const int t = threadIdx.x;
    if (t < 128) {
        float s = part[t] + part[128 + t] + part[256 + t] + part[384 + t];
        g_colpart[((size_t)n * 32 + blockIdx.y) * HW + j0 + t] = s;
    }
}

// ---------------- K2b: reduce column partials -> colsum -------------------
__global__ void k_colreduce()
{
    const int idx = blockIdx.x * 256 + threadIdx.x;   // over N*HW = 16384
    const int n = idx >> 12;
    const int j = idx & 4095;
    float s = 0.f;
#pragma unroll
    for (int b = 0; b < 32; b++)
        s += g_colpart[((size_t)n * 32 + b) * HW + j];
    g_colsum[idx] = s;
}

// ---------------- K3: VsT[d][j] = fp16(256 * V[j,d] / colsum[j]) ----------
__global__ void k_vscale()
{
    __shared__ float t[32][33];
    const int n = blockIdx.z;
    const int j0 = blockIdx.x * 32;
    const int d0 = blockIdx.y * 32;
    const int tx = threadIdx.x, ty = threadIdx.y;
    const __half* qb = g_qkv + (size_t)n * OC * HW;
    t[ty][tx] = __half2float(qb[(size_t)(j0 + ty) * 384 + 256 + d0 + tx]);
    __syncthreads();
    const int j = j0 + tx;
    g_VsT[((size_t)n * E_DIM + d0 + ty) * HW + j] =
        __float2half_rn(t[tx][ty] * (VS_SCALE / g_colsum[n * HW + j]));
}

// ---------------- K4: O_partial = S' @ VsT^T (fp16 MMA, split-K) ----------
__global__ void __launch_bounds__(256, 2) k_pv()
{
    __shared__ __half As[2][128][40];
    __shared__ __half Bs[2][128][40];
    const int n = blockIdx.z;
    const int i0 = blockIdx.y * 128;
    const int split = blockIdx.x;
    const int jbase = split * (HW / KSPLIT);
    const __half* Abase = g_S + (size_t)n * HW * HW + (size_t)i0 * HW + jbase;
    const __half* Bbase = g_VsT + (size_t)n * E_DIM * HW + jbase;
    float c[2][8][4] = {};
    gemm_async_f16(Abase, HW, Bbase, HW, (HW / KSPLIT) / 32, As, Bs, c, threadIdx.x);

    const int lane = threadIdx.x & 31, warp = threadIdx.x >> 5;
    const int gid = lane >> 2, tig = lane & 3, wm = warp & 3, wn = warp >> 2;
    __half* Ob = g_Opart + ((size_t)split * N_BATCH + n) * HW * E_DIM;
#pragma unroll
    for (int ms = 0; ms < 2; ms++) {
        const int r0 = i0 + wm * 32 + ms * 16 + gid;
#pragma unroll
        for (int ns = 0; ns < 8; ns++) {
            const int col = wn * 64 + ns * 8 + 2 * tig;
            *(__half2*)(Ob + (size_t)r0 * E_DIM + col) =
                __halves2half2(__float2half_rn(c[ms][ns][0] * VS_INV),
                               __float2half_rn(c[ms][ns][1] * VS_INV));
            *(__half2*)(Ob + (size_t)(r0 + 8) * E_DIM + col) =
                __halves2half2(__float2half_rn(c[ms][ns][2] * VS_INV),
                               __float2half_rn(c[ms][ns][3] * VS_INV));
        }
    }
}

// ---------------- K5: output projection + split-K reduce ------------------
// y[n,c,p] = sum_e Wout[c,e] * (Opart0+Opart1)[n][e*4096 + p] + bout[c]
__global__ void __launch_bounds__(256, 2) k_proj(
    float* __restrict__ out, const float* __restrict__ Wout,
    const float* __restrict__ bout)
{
    __shared__ uint32_t As[128][20];
    __shared__ uint32_t Bs[128][20];
    const int n = blockIdx.z;
    const int c0 = blockIdx.y * 128;
    const int p0 = blockIdx.x * 128;
    const int tid = threadIdx.x;
    const float* Abase = Wout + (size_t)c0 * E_DIM;                               // [M][K] ld 128
    const __half* B0 = g_Opart + ((size_t)0 * N_BATCH + n) * HW * E_DIM + p0;     // flat [K=128][N]
    const __half* B1 = g_Opart + ((size_t)1 * N_BATCH + n) * HW * E_DIM + p0;

    const int lane = tid & 31, warp = tid >> 5;
    const int gid = lane >> 2, tig = lane & 3;
    const int wm = warp & 3, wn = warp >> 2;
    float c[2][8][4] = {};

    for (int kt = 0; kt < E_DIM / 16; kt++) {
        const int k0 = kt * 16;
#pragma unroll
        for (int i = 0; i < 2; i++) {
            int t = tid + 256 * i;
            int row = t >> 2, c4 = (t & 3) << 2;
            float4 v = __ldg(reinterpret_cast<const float4*>(
                Abase + (size_t)row * E_DIM + k0 + c4));
            As[row][c4 + 0] = f2tf32(v.x);
            As[row][c4 + 1] = f2tf32(v.y);
            As[row][c4 + 2] = f2tf32(v.z);
            As[row][c4 + 3] = f2tf32(v.w);
        }
#pragma unroll
        for (int i = 0; i < 2; i++) {
            int t = tid + 256 * i;
            int k = t >> 5, c4 = (t & 31) << 2;
            size_t off = (size_t)(k0 + k) * HW + c4;
            __half2 p01 = *(const __half2*)(B0 + off);
            __half2 p23 = *(const __half2*)(B0 + off + 2);
            __half2 q01 = *(const __half2*)(B1 + off);
            __half2 q23 = *(const __half2*)(B1 + off + 2);
            Bs[c4 + 0][k] = f2tf32(__half2float(p01.x) + __half2float(q01.x));
            Bs[c4 + 1][k] = f2tf32(__half2float(p01.y) + __half2float(q01.y));
            Bs[c4 + 2][k] = f2tf32(__half2float(p23.x) + __half2float(q23.x));
            Bs[c4 + 3][k] = f2tf32(__half2float(p23.y) + __half2float(q23.y));
        }
        __syncthreads();

#pragma unroll
        for (int kk = 0; kk < 2; kk++) {
            const int kb = kk << 3;
            uint32_t a[2][4];
#pragma unroll
            for (int ms = 0; ms < 2; ms++) {
                int rb = wm * 32 + ms * 16;
                a[ms][0] = As[rb + gid][kb + tig];
                a[ms][1] = As[rb + gid + 8][kb + tig];
                a[ms][2] = As[rb + gid][kb + tig + 4];
                a[ms][3] = As[rb + gid + 8][kb + tig + 4];
            }
            uint32_t b[8][2];
#pragma unroll
            for (int ns = 0; ns < 8; ns++) {
                int nb = wn * 64 + ns * 8;
                b[ns][0] = Bs[nb + gid][kb + tig];
                b[ns][1] = Bs[nb + gid][kb + tig + 4];
            }
#pragma unroll
            for (int ms = 0; ms < 2; ms++)
#pragma unroll
                for (int ns = 0; ns < 8; ns++)
                    mma_tf32(c[ms][ns], a[ms], b[ns]);
        }
        __syncthreads();
    }

    float* Yb = out + (size_t)n * C_IN * HW;
#pragma unroll
    for (int ms = 0; ms < 2; ms++) {
        const int r0 = c0 + wm * 32 + ms * 16 + gid;
        const float b0 = bout[r0], b1 = bout[r0 + 8];
#pragma unroll
        for (int ns = 0; ns < 8; ns++) {
            const int col = p0 + wn * 64 + ns * 8 + 2 * tig;
            *(float2*)(Yb + (size_t)r0 * HW + col) =
                make_float2(c[ms][ns][0] + b0, c[ms][ns][1] + b0);
            *(float2*)(Yb + (size_t)(r0 + 8) * HW + col) =
                make_float2(c[ms][ns][2] + b1, c[ms][ns][3] + b1);
        }
    }
}

// ---------------- launch ---------------------------------------------------
extern "C" void kernel_launch(void* const* d_in, const int* in_sizes, int n_in,
                              void* d_out, int out_size)
{
    (void)in_sizes; (void)n_in; (void)out_size;
    const float* x    = (const float*)d_in[0];
    const float* Wqkv = (const float*)d_in[1];
    const float* bqkv = (const float*)d_in[2];
    const float* Wout = (const float*)d_in[3];
    const float* bout = (const float*)d_in[4];
    float* out = (float*)d_out;

    dim3 blk(256);
    k_qkv<<<dim3(HW / 128, OC / 128, N_BATCH), blk>>>(x, Wqkv, bqkv);
    k_scores<<<dim3(HW / 128, HW / 128, N_BATCH), blk>>>();
    k_colreduce<<<(N_BATCH * HW) / 256, 256>>>();
    k_vscale<<<dim3(HW / 32, E_DIM / 32, N_BATCH), dim3(32, 32)>>>();
    k_pv<<<dim3(KSPLIT, HW / 128, N_BATCH), blk>>>();
    k_proj<<<dim3(HW / 128, C_IN / 128, N_BATCH), blk>>>(out, Wout, bout);
}

// round 10
// speedup vs baseline: 2.1057x; 1.0535x over previous
#include <cuda_runtime.h>
#include <cuda_fp16.h>
#include <cstdint>
#include <cstddef>

#define N_BATCH 4
#define C_IN    256
#define HW      4096
#define E_DIM   128
#define OC      384   // 3*E
#define KSPLIT  4
#define VS_SCALE 256.0f
#define VS_INV   0.00390625f

// ---------------- scratch (static device globals; no runtime allocation) ----------------
__device__ __half g_qkv[(size_t)N_BATCH * OC * HW];          //  12.6 MB (n,o,p) flat, fp16
__device__ __half g_S[(size_t)N_BATCH * HW * HW];            // 134.2 MB exp(scores), fp16
__device__ float  g_colpart[(size_t)N_BATCH * 32 * HW];      //   2.1 MB per-i-block column partials
__device__ __half g_VsT[(size_t)N_BATCH * E_DIM * HW];       //   4.2 MB (n,d,j) = 256*V^T/colsum, fp16
__device__ __half g_Opart[(size_t)KSPLIT * N_BATCH * HW * E_DIM]; // 16.8 MB split-K partials, fp16

// ---------------- helpers ----------------
__device__ __forceinline__ uint32_t f2tf32(float x) {
    uint32_t r;
    asm("cvt.rna.tf32.f32 %0, %1;" : "=r"(r) : "f"(x));
    return r;
}

// fast exp for |x| <~ 2 : ~1e-7 relative error, pure FMA/ALU (avoids MUFU throughput wall)
__device__ __forceinline__ float fexp(float x) {
    float t = x * 1.4426950408889634f;
    int   ri = __float2int_rn(t);
    float f = t - (float)ri;
    float u = f * 0.6931471805599453f;
    float p = 1.3888889e-3f;
    p = fmaf(p, u, 8.3333333e-3f);
    p = fmaf(p, u, 4.1666667e-2f);
    p = fmaf(p, u, 1.6666667e-1f);
    p = fmaf(p, u, 0.5f);
    p = fmaf(p, u, 1.0f);
    p = fmaf(p, u, 1.0f);
    return p * __int_as_float((ri + 127) << 23);
}

__device__ __forceinline__ void mma_tf32(float c[4],
                                         const uint32_t a[4],
                                         const uint32_t b[2]) {
    asm volatile(
        "mma.sync.aligned.m16n8k8.row.col.f32.tf32.tf32.f32 "
        "{%0,%1,%2,%3}, {%4,%5,%6,%7}, {%8,%9}, {%0,%1,%2,%3};"
        : "+f"(c[0]), "+f"(c[1]), "+f"(c[2]), "+f"(c[3])
        : "r"(a[0]), "r"(a[1]), "r"(a[2]), "r"(a[3]), "r"(b[0]), "r"(b[1]));
}
__device__ __forceinline__ void mma_f16(float c[4],
                                        const uint32_t a[4],
                                        const uint32_t b[2]) {
    asm volatile(
        "mma.sync.aligned.m16n8k16.row.col.f32.f16.f16.f32 "
        "{%0,%1,%2,%3}, {%4,%5,%6,%7}, {%8,%9}, {%0,%1,%2,%3};"
        : "+f"(c[0]), "+f"(c[1]), "+f"(c[2]), "+f"(c[3])
        : "r"(a[0]), "r"(a[1]), "r"(a[2]), "r"(a[3]), "r"(b[0]), "r"(b[1]));
}

// ldmatrix x4: four 8x8 b16 fragments in one shared-pipe instruction
__device__ __forceinline__ void ldsm_x4(uint32_t& r0, uint32_t& r1,
                                        uint32_t& r2, uint32_t& r3,
                                        const void* p) {
    uint32_t addr = (uint32_t)__cvta_generic_to_shared(p);
    asm volatile("ldmatrix.sync.aligned.m8n8.x4.shared.b16 {%0,%1,%2,%3}, [%4];\n"
                 : "=r"(r0), "=r"(r1), "=r"(r2), "=r"(r3) : "r"(addr));
}

// cp.async 16B helpers
__device__ __forceinline__ void cp16(void* smem_dst, const void* gsrc) {
    uint32_t s = (uint32_t)__cvta_generic_to_shared(smem_dst);
    asm volatile("cp.async.cg.shared.global [%0], [%1], 16;\n" :: "r"(s), "l"(gsrc));
}
__device__ __forceinline__ void cp_commit() {
    asm volatile("cp.async.commit_group;\n");
}
template <int N>
__device__ __forceinline__ void cp_wait() {
    asm volatile("cp.async.wait_group %0;\n" :: "n"(N));
}

// ================= async double-buffered fp16 GEMM core (ldmatrix) ========
// C[128x128] fp32 accum, A/B fp16 [row][k] global, k-tile 32.
// 256 threads = 8 warps 4(M)x2(N), warp tile 32x64.
// Smem row stride 40 halfs (80B): 16B-aligned cp.async dsts; ldmatrix rows at
// 20-word stride cover all 32 banks conflict-free.
__device__ __forceinline__ void gemm_async_f16(
    const __half* __restrict__ Abase, int lda,
    const __half* __restrict__ Bbase, int ldb,
    int ktiles,
    __half (*As)[128][40], __half (*Bs)[128][40],
    float c[2][8][4], int tid)
{
    const int lane = tid & 31, warp = tid >> 5;
    const int wm = warp & 3, wn = warp >> 2;
    const int r0 = tid >> 2, h8 = (tid & 3) << 3;  // 8 halfs = 16 B per cp
    const int lrow = lane & 15, lcol = (lane >> 4) << 3;  // ldmatrix addressing

    auto issue = [&](int kt, int buf) {
        const int k0 = kt * 32;
        cp16(&As[buf][r0][h8],      Abase + (size_t)r0 * lda + k0 + h8);
        cp16(&As[buf][r0 + 64][h8], Abase + (size_t)(r0 + 64) * lda + k0 + h8);
        cp16(&Bs[buf][r0][h8],      Bbase + (size_t)r0 * ldb + k0 + h8);
        cp16(&Bs[buf][r0 + 64][h8], Bbase + (size_t)(r0 + 64) * ldb + k0 + h8);
        cp_commit();
    };

    issue(0, 0);
    for (int kt = 0; kt < ktiles; kt++) {
        const int buf = kt & 1;
        if (kt + 1 < ktiles) { issue(kt + 1, (kt + 1) & 1); cp_wait<1>(); }
        else                 { cp_wait<0>(); }
        __syncthreads();

#pragma unroll
        for (int kk = 0; kk < 2; kk++) {
            const int kb = kk << 4;
            uint32_t a[2][4];
#pragma unroll
            for (int ms = 0; ms < 2; ms++) {
                int rb = wm * 32 + ms * 16;
                ldsm_x4(a[ms][0], a[ms][1], a[ms][2], a[ms][3],
                        &As[buf][rb + lrow][kb + lcol]);
            }
            uint32_t b[8][2];
#pragma unroll
            for (int g = 0; g < 4; g++) {
                int nb = wn * 64 + g * 16;
                uint32_t m0, m1, m2, m3;
                ldsm_x4(m0, m1, m2, m3, &Bs[buf][nb + lrow][kb + lcol]);
                b[2 * g][0]     = m0; b[2 * g][1]     = m2;
                b[2 * g + 1][0] = m1; b[2 * g + 1][1] = m3;
            }
#pragma unroll
            for (int ms = 0; ms < 2; ms++)
#pragma unroll
                for (int ns = 0; ns < 8; ns++)
                    mma_f16(c[ms][ns], a[ms], b[ns]);
        }
        __syncthreads();
    }
}

// ================= LDG+cvt tf32 GEMM core (external fp32 inputs) ==========
// B_KN=true : global B is [K][N] row-major (transposed while staging to smem)
template <bool B_KN>
__device__ __forceinline__ void gemm_main(
    const float* __restrict__ Abase, int lda,
    const float* __restrict__ Bbase, int ldb,
    int ktiles,
    uint32_t (*As)[20], uint32_t (*Bs)[20],
    float c[2][8][4], int tid)
{
    const int lane = tid & 31, warp = tid >> 5;
    const int gid = lane >> 2, tig = lane & 3;
    const int wm = warp & 3, wn = warp >> 2;

    for (int kt = 0; kt < ktiles; kt++) {
        const int k0 = kt * 16;
#pragma unroll
        for (int i = 0; i < 2; i++) {
            int t = tid + 256 * i;
            int row = t >> 2, c4 = (t & 3) << 2;
            float4 v = __ldg(reinterpret_cast<const float4*>(
                Abase + (size_t)row * lda + k0 + c4));
            As[row][c4 + 0] = f2tf32(v.x);
            As[row][c4 + 1] = f2tf32(v.y);
            As[row][c4 + 2] = f2tf32(v.z);
            As[row][c4 + 3] = f2tf32(v.w);
        }
        if (B_KN) {
#pragma unroll
            for (int i = 0; i < 2; i++) {
                int t = tid + 256 * i;
                int k = t >> 5, c4 = (t & 31) << 2;
                float4 v = __ldg(reinterpret_cast<const float4*>(
                    Bbase + (size_t)(k0 + k) * ldb + c4));
                Bs[c4 + 0][k] = f2tf32(v.x);
                Bs[c4 + 1][k] = f2tf32(v.y);
                Bs[c4 + 2][k] = f2tf32(v.z);
                Bs[c4 + 3][k] = f2tf32(v.w);
            }
        } else {
#pragma unroll
            for (int i = 0; i < 2; i++) {
                int t = tid + 256 * i;
                int row = t >> 2, c4 = (t & 3) << 2;
                float4 v = __ldg(reinterpret_cast<const float4*>(
                    Bbase + (size_t)row * ldb + k0 + c4));
                Bs[row][c4 + 0] = f2tf32(v.x);
                Bs[row][c4 + 1] = f2tf32(v.y);
                Bs[row][c4 + 2] = f2tf32(v.z);
                Bs[row][c4 + 3] = f2tf32(v.w);
            }
        }
        __syncthreads();

#pragma unroll
        for (int kk = 0; kk < 2; kk++) {
            const int kb = kk << 3;
            uint32_t a[2][4];
#pragma unroll
            for (int ms = 0; ms < 2; ms++) {
                int rb = wm * 32 + ms * 16;
                a[ms][0] = As[rb + gid][kb + tig];
                a[ms][1] = As[rb + gid + 8][kb + tig];
                a[ms][2] = As[rb + gid][kb + tig + 4];
                a[ms][3] = As[rb + gid + 8][kb + tig + 4];
            }
            uint32_t b[8][2];
#pragma unroll
            for (int ns = 0; ns < 8; ns++) {
                int nb = wn * 64 + ns * 8;
                b[ns][0] = Bs[nb + gid][kb + tig];
                b[ns][1] = Bs[nb + gid][kb + tig + 4];
            }
#pragma unroll
            for (int ms = 0; ms < 2; ms++)
#pragma unroll
                for (int ns = 0; ns < 8; ns++)
                    mma_tf32(c[ms][ns], a[ms], b[ns]);
        }
        __syncthreads();
    }
}

// ---------------- K1: QKV projection (stores fp16) ------------------------
// qkv[n,o,p] = fp16( sum_c Wqkv[o,c] * x[n,c,p] + bqkv[o] )
__global__ void __launch_bounds__(256, 2) k_qkv(
    const float* __restrict__ x, const float* __restrict__ Wqkv,
    const float* __restrict__ bqkv)
{
    __shared__ uint32_t As[128][20];
    __shared__ uint32_t Bs[128][20];
    const int n = blockIdx.z;
    const int m0 = blockIdx.y * 128;
    const int p0 = blockIdx.x * 128;
    const float* Abase = Wqkv + (size_t)m0 * C_IN;               // [M][K]
    const float* Bbase = x + (size_t)n * C_IN * HW + p0;         // [K][N]
    float c[2][8][4] = {};
    gemm_main<true>(Abase, C_IN, Bbase, HW, C_IN / 16, As, Bs, c, threadIdx.x);

    const int lane = threadIdx.x & 31, warp = threadIdx.x >> 5;
    const int gid = lane >> 2, tig = lane & 3, wm = warp & 3, wn = warp >> 2;
    __half* Cb = g_qkv + (size_t)n * OC * HW;
#pragma unroll
    for (int ms = 0; ms < 2; ms++) {
        const int r0 = m0 + wm * 32 + ms * 16 + gid;
        const float b0 = bqkv[r0], b1 = bqkv[r0 + 8];
#pragma unroll
        for (int ns = 0; ns < 8; ns++) {
            const int col = p0 + wn * 64 + ns * 8 + 2 * tig;
            *(__half2*)(Cb + (size_t)r0 * HW + col) =
                __halves2half2(__float2half_rn(c[ms][ns][0] + b0),
                               __float2half_rn(c[ms][ns][1] + b0));
            *(__half2*)(Cb + (size_t)(r0 + 8) * HW + col) =
                __halves2half2(__float2half_rn(c[ms][ns][2] + b1),
                               __float2half_rn(c[ms][ns][3] + b1));
        }
    }
}

// ---------------- K2: S' = fp16(exp(Q K^T / 64)), column partial sums -----
// Faithful reshape: Q[i,k] = qkv_flat[i*384 + k], K[j,k] = qkv_flat[j*384 + 128 + k]
// Epilogue stages the 128x128 fp16 tile through smem -> 16B coalesced STG.
__global__ void __launch_bounds__(256, 2) k_scores()
{
    // one 40 KB arena: GEMM double buffers, then reused as the store-staging tile
    __shared__ __align__(16) __half smem_raw[2 * 2 * 128 * 40];
    __half (*As)[128][40] = reinterpret_cast<__half (*)[128][40]>(smem_raw);
    __half (*Bs)[128][40] = reinterpret_cast<__half (*)[128][40]>(smem_raw + 2 * 128 * 40);

    const int n = blockIdx.z;
    const int i0 = blockIdx.y * 128;
    const int j0 = blockIdx.x * 128;
    const __half* qb = g_qkv + (size_t)n * OC * HW;
    const __half* Abase = qb + (size_t)i0 * 384;          // Q rows  [M][K] ld 384
    const __half* Bbase = qb + (size_t)j0 * 384 + 128;    // K rows  [N][K] ld 384
    float c[2][8][4] = {};
    gemm_async_f16(Abase, 384, Bbase, 384, 128 / 32, As, Bs, c, threadIdx.x);

    const int tid = threadIdx.x;
    const int lane = tid & 31, warp = tid >> 5;
    const int gid = lane >> 2, tig = lane & 3, wm = warp & 3, wn = warp >> 2;
    const float scale = 0.015625f;  // 1/sqrt(4096)

    // staging views into the arena (mainloop done; last loop iter ended with sync)
    __half2* sm = reinterpret_cast<__half2*>(smem_raw);       // [row][h2 col], stride 68 h2 (272 B)
    float* part = reinterpret_cast<float*>(sm + 128 * 68);    // 512 floats, disjoint from sm tile

    float csum[8][2];
#pragma unroll
    for (int ns = 0; ns < 8; ns++) { csum[ns][0] = 0.f; csum[ns][1] = 0.f; }

#pragma unroll
    for (int ms = 0; ms < 2; ms++) {
        const int row = wm * 32 + ms * 16 + gid;
#pragma unroll
        for (int ns = 0; ns < 8; ns++) {
            const int ch2 = wn * 32 + ns * 4 + tig;   // half2 column
            // round exp to fp16 HERE; colsum adds the ROUNDED values so the
            // normalization matches the stored matrix exactly.
            __half h0 = __float2half_rn(fexp(c[ms][ns][0] * scale));
            __half h1 = __float2half_rn(fexp(c[ms][ns][1] * scale));
            __half h2 = __float2half_rn(fexp(c[ms][ns][2] * scale));
            __half h3 = __float2half_rn(fexp(c[ms][ns][3] * scale));
            sm[row * 68 + ch2]       = __halves2half2(h0, h1);
            sm[(row + 8) * 68 + ch2] = __halves2half2(h2, h3);
            csum[ns][0] += __half2float(h0) + __half2float(h2);
            csum[ns][1] += __half2float(h1) + __half2float(h3);
        }
    }
    // deterministic column reduction: shfl across row-groups, smem across warps
#pragma unroll
    for (int ns = 0; ns < 8; ns++) {
#pragma unroll
        for (int jj = 0; jj < 2; jj++) {
            float v = csum[ns][jj];
            v += __shfl_xor_sync(0xffffffffu, v, 4);
            v += __shfl_xor_sync(0xffffffffu, v, 8);
            v += __shfl_xor_sync(0xffffffffu, v, 16);
            if (gid == 0)
                part[wm * 128 + wn * 64 + ns * 8 + 2 * tig + jj] = v;
        }
    }
    __syncthreads();

    // coalesced 16B stores: 2048 chunks of 8 halfs, 8 per thread
    __half* Sb = g_S + (size_t)n * HW * HW;
#pragma unroll
    for (int it = 0; it < 8; it++) {
        int q = it * 256 + tid;
        int row = q >> 4, ch = q & 15;
        float4 v = *reinterpret_cast<const float4*>(sm + row * 68 + ch * 4);
        *reinterpret_cast<float4*>(Sb + (size_t)(i0 + row) * HW + j0 + ch * 8) = v;
    }
    if (tid < 128) {
        float s = part[tid] + part[128 + tid] + part[256 + tid] + part[384 + tid];
        g_colpart[((size_t)n * 32 + blockIdx.y) * HW + j0 + tid] = s;
    }
}

// ---------------- K3: colsum reduce + VsT[d][j] = fp16(256*V[j,d]/colsum[j])
__global__ void k_vscale()
{
    __shared__ float ps[32][33];
    __shared__ float t[32][33];
    const int n = blockIdx.y;
    const int j0 = blockIdx.x * 32;
    const int tx = threadIdx.x, ty = threadIdx.y;

    // reduce the 32 per-i-block partials for columns j0..j0+31 (deterministic tree)
    ps[ty][tx] = g_colpart[((size_t)n * 32 + ty) * HW + j0 + tx];
    __syncthreads();
#pragma unroll
    for (int s = 16; s > 0; s >>= 1) {
        if (ty < s) ps[ty][tx] += ps[ty + s][tx];
        __syncthreads();
    }
    const float inv = VS_SCALE / ps[0][tx];   // for column j = j0 + tx

    const __half* qb = g_qkv + (size_t)n * OC * HW;
    __half* Vb = g_VsT + (size_t)n * E_DIM * HW;
#pragma unroll
    for (int dd = 0; dd < 4; dd++) {
        t[ty][tx] = __half2float(qb[(size_t)(j0 + ty) * 384 + 256 + dd * 32 + tx]);
        __syncthreads();
        Vb[(size_t)(dd * 32 + ty) * HW + j0 + tx] = __float2half_rn(t[tx][ty] * inv);
        __syncthreads();
    }
}

// ---------------- K4: O_partial = S' @ VsT^T (fp16 MMA, split-K x4) -------
__global__ void __launch_bounds__(256, 2) k_pv()
{
    __shared__ __half As[2][128][40];
    __shared__ __half Bs[2][128][40];
    const int n = blockIdx.z;
    const int i0 = blockIdx.y * 128;
    const int split = blockIdx.x;
    const int jbase = split * (HW / KSPLIT);
    const __half* Abase = g_S + (size_t)n * HW * HW + (size_t)i0 * HW + jbase;
    const __half* Bbase = g_VsT + (size_t)n * E_DIM * HW + jbase;
    float c[2][8][4] = {};
    gemm_async_f16(Abase, HW, Bbase, HW, (HW / KSPLIT) / 32, As, Bs, c, threadIdx.x);

    const int lane = threadIdx.x & 31, warp = threadIdx.x >> 5;
    const int gid = lane >> 2, tig = lane & 3, wm = warp & 3, wn = warp >> 2;
    __half* Ob = g_Opart + ((size_t)split * N_BATCH + n) * HW * E_DIM;
#pragma unroll
    for (int ms = 0; ms < 2; ms++) {
        const int r0 = i0 + wm * 32 + ms * 16 + gid;
#pragma unroll
        for (int ns = 0; ns < 8; ns++) {
            const int col = wn * 64 + ns * 8 + 2 * tig;
            *(__half2*)(Ob + (size_t)r0 * E_DIM + col) =
                __halves2half2(__float2half_rn(c[ms][ns][0] * VS_INV),
                               __float2half_rn(c[ms][ns][1] * VS_INV));
            *(__half2*)(Ob + (size_t)(r0 + 8) * E_DIM + col) =
                __halves2half2(__float2half_rn(c[ms][ns][2] * VS_INV),
                               __float2half_rn(c[ms][ns][3] * VS_INV));
        }
    }
}

// ---------------- K5: output projection + split-K reduce ------------------
// y[n,c,p] = sum_e Wout[c,e] * (sum_s Opart_s)[n][e*4096 + p] + bout[c]
__global__ void __launch_bounds__(256, 2) k_proj(
    float* __restrict__ out, const float* __restrict__ Wout,
    const float* __restrict__ bout)
{
    __shared__ uint32_t As[128][20];
    __shared__ uint32_t Bs[128][20];
    const int n = blockIdx.z;
    const int c0 = blockIdx.y * 128;
    const int p0 = blockIdx.x * 128;
    const int tid = threadIdx.x;
    const float* Abase = Wout + (size_t)c0 * E_DIM;                               // [M][K] ld 128
    const __half* Bp[KSPLIT];
#pragma unroll
    for (int s = 0; s < KSPLIT; s++)
        Bp[s] = g_Opart + ((size_t)s * N_BATCH + n) * HW * E_DIM + p0;            // flat [K=128][N]

    const int lane = tid & 31, warp = tid >> 5;
    const int gid = lane >> 2, tig = lane & 3;
    const int wm = warp & 3, wn = warp >> 2;
    float c[2][8][4] = {};

    for (int kt = 0; kt < E_DIM / 16; kt++) {
        const int k0 = kt * 16;
#pragma unroll
        for (int i = 0; i < 2; i++) {
            int t = tid + 256 * i;
            int row = t >> 2, c4 = (t & 3) << 2;
            float4 v = __ldg(reinterpret_cast<const float4*>(
                Abase + (size_t)row * E_DIM + k0 + c4));
            As[row][c4 + 0] = f2tf32(v.x);
            As[row][c4 + 1] = f2tf32(v.y);
            As[row][c4 + 2] = f2tf32(v.z);
            As[row][c4 + 3] = f2tf32(v.w);
        }
#pragma unroll
        for (int i = 0; i < 2; i++) {
            int t = tid + 256 * i;
            int k = t >> 5, c4 = (t & 31) << 2;
            size_t off = (size_t)(k0 + k) * HW + c4;
            float s0 = 0.f, s1 = 0.f, s2 = 0.f, s3 = 0.f;
#pragma unroll
            for (int s = 0; s < KSPLIT; s++) {
                __half2 p01 = *(const __half2*)(Bp[s] + off);
                __half2 p23 = *(const __half2*)(Bp[s] + off + 2);
                s0 += __half2float(p01.x); s1 += __half2float(p01.y);
                s2 += __half2float(p23.x); s3 += __half2float(p23.y);
            }
            Bs[c4 + 0][k] = f2tf32(s0);
            Bs[c4 + 1][k] = f2tf32(s1);
            Bs[c4 + 2][k] = f2tf32(s2);
            Bs[c4 + 3][k] = f2tf32(s3);
        }
        __syncthreads();

#pragma unroll
        for (int kk = 0; kk < 2; kk++) {
            const int kb = kk << 3;
            uint32_t a[2][4];
#pragma unroll
            for (int ms = 0; ms < 2; ms++) {
                int rb = wm * 32 + ms * 16;
                a[ms][0] = As[rb + gid][kb + tig];
                a[ms][1] = As[rb + gid + 8][kb + tig];
                a[ms][2] = As[rb + gid][kb + tig + 4];
                a[ms][3] = As[rb + gid + 8][kb + tig + 4];
            }
            uint32_t b[8][2];
#pragma unroll
            for (int ns = 0; ns < 8; ns++) {
                int nb = wn * 64 + ns * 8;
                b[ns][0] = Bs[nb + gid][kb + tig];
                b[ns][1] = Bs[nb + gid][kb + tig + 4];
            }
#pragma unroll
            for (int ms = 0; ms < 2; ms++)
#pragma unroll
                for (int ns = 0; ns < 8; ns++)
                    mma_tf32(c[ms][ns], a[ms], b[ns]);
        }
        __syncthreads();
    }

    float* Yb = out + (size_t)n * C_IN * HW;
#pragma unroll
    for (int ms = 0; ms < 2; ms++) {
        const int r0 = c0 + wm * 32 + ms * 16 + gid;
        const float b0 = bout[r0], b1 = bout[r0 + 8];
#pragma unroll
        for (int ns = 0; ns < 8; ns++) {
            const int col = p0 + wn * 64 + ns * 8 + 2 * tig;
            *(float2*)(Yb + (size_t)r0 * HW + col) =
                make_float2(c[ms][ns][0] + b0, c[ms][ns][1] + b0);
            *(float2*)(Yb + (size_t)(r0 + 8) * HW + col) =
                make_float2(c[ms][ns][2] + b1, c[ms][ns][3] + b1);
        }
    }
}

// ---------------- launch ---------------------------------------------------
extern "C" void kernel_launch(void* const* d_in, const int* in_sizes, int n_in,
                              void* d_out, int out_size)
{
    (void)in_sizes; (void)n_in; (void)out_size;
    const float* x    = (const float*)d_in[0];
    const float* Wqkv = (const float*)d_in[1];
    const float* bqkv = (const float*)d_in[2];
    const float* Wout = (const float*)d_in[3];
    const float* bout = (const float*)d_in[4];
    float* out = (float*)d_out;

    dim3 blk(256);
    k_qkv<<<dim3(HW / 128, OC / 128, N_BATCH), blk>>>(x, Wqkv, bqkv);
    k_scores<<<dim3(HW / 128, HW / 128, N_BATCH), blk>>>();
    k_vscale<<<dim3(HW / 32, N_BATCH), dim3(32, 32)>>>();
    k_pv<<<dim3(KSPLIT, HW / 128, N_BATCH), blk>>>();
    k_proj<<<dim3(HW / 128, C_IN / 128, N_BATCH), blk>>>(out, Wout, bout);
}

// round 11
// speedup vs baseline: 2.1611x; 1.0263x over previous
#include <cuda_runtime.h>
#include <cuda_fp16.h>
#include <cstdint>
#include <cstddef>

#define N_BATCH 4
#define C_IN    256
#define HW      4096
#define E_DIM   128
#define OC      384   // 3*E
#define KSPLIT  8
#define VS_SCALE 256.0f
#define VS_INV   0.00390625f

#define NSTAGE  3
#define SMEM_DYN (2 * NSTAGE * 128 * 40 * (int)sizeof(__half))   // 61440 B

// ---------------- scratch (static device globals; no runtime allocation) ----------------
__device__ __half g_qkv[(size_t)N_BATCH * OC * HW];          //  12.6 MB (n,o,p) flat, fp16
__device__ __half g_S[(size_t)N_BATCH * HW * HW];            // 134.2 MB exp(scores), fp16
__device__ float  g_colpart[(size_t)N_BATCH * 32 * HW];      //   2.1 MB per-i-block column partials
__device__ __half g_VsT[(size_t)N_BATCH * E_DIM * HW];       //   4.2 MB (n,d,j) = 256*V^T/colsum, fp16
__device__ __half g_Opart[(size_t)KSPLIT * N_BATCH * HW * E_DIM]; // 33.6 MB split-K partials, fp16

// ---------------- helpers ----------------
__device__ __forceinline__ uint32_t f2tf32(float x) {
    uint32_t r;
    asm("cvt.rna.tf32.f32 %0, %1;" : "=r"(r) : "f"(x));
    return r;
}

// fast exp for |x| <~ 2 : ~1e-7 relative error, pure FMA/ALU (avoids MUFU throughput wall)
__device__ __forceinline__ float fexp(float x) {
    float t = x * 1.4426950408889634f;
    int   ri = __float2int_rn(t);
    float f = t - (float)ri;
    float u = f * 0.6931471805599453f;
    float p = 1.3888889e-3f;
    p = fmaf(p, u, 8.3333333e-3f);
    p = fmaf(p, u, 4.1666667e-2f);
    p = fmaf(p, u, 1.6666667e-1f);
    p = fmaf(p, u, 0.5f);
    p = fmaf(p, u, 1.0f);
    p = fmaf(p, u, 1.0f);
    return p * __int_as_float((ri + 127) << 23);
}

__device__ __forceinline__ void mma_tf32(float c[4],
                                         const uint32_t a[4],
                                         const uint32_t b[2]) {
    asm volatile(
        "mma.sync.aligned.m16n8k8.row.col.f32.tf32.tf32.f32 "
        "{%0,%1,%2,%3}, {%4,%5,%6,%7}, {%8,%9}, {%0,%1,%2,%3};"
        : "+f"(c[0]), "+f"(c[1]), "+f"(c[2]), "+f"(c[3])
        : "r"(a[0]), "r"(a[1]), "r"(a[2]), "r"(a[3]), "r"(b[0]), "r"(b[1]));
}
__device__ __forceinline__ void mma_f16(float c[4],
                                        const uint32_t a[4],
                                        const uint32_t b[2]) {
    asm volatile(
        "mma.sync.aligned.m16n8k16.row.col.f32.f16.f16.f32 "
        "{%0,%1,%2,%3}, {%4,%5,%6,%7}, {%8,%9}, {%0,%1,%2,%3};"
        : "+f"(c[0]), "+f"(c[1]), "+f"(c[2]), "+f"(c[3])
        : "r"(a[0]), "r"(a[1]), "r"(a[2]), "r"(a[3]), "r"(b[0]), "r"(b[1]));
}

// ldmatrix x4: four 8x8 b16 fragments in one shared-pipe instruction
__device__ __forceinline__ void ldsm_x4(uint32_t& r0, uint32_t& r1,
                                        uint32_t& r2, uint32_t& r3,
                                        const void* p) {
    uint32_t addr = (uint32_t)__cvta_generic_to_shared(p);
    asm volatile("ldmatrix.sync.aligned.m8n8.x4.shared.b16 {%0,%1,%2,%3}, [%4];\n"
                 : "=r"(r0), "=r"(r1), "=r"(r2), "=r"(r3) : "r"(addr));
}

// cp.async 16B helpers
__device__ __forceinline__ void cp16(void* smem_dst, const void* gsrc) {
    uint32_t s = (uint32_t)__cvta_generic_to_shared(smem_dst);
    asm volatile("cp.async.cg.shared.global [%0], [%1], 16;\n" :: "r"(s), "l"(gsrc));
}
__device__ __forceinline__ void cp_commit() {
    asm volatile("cp.async.commit_group;\n");
}
template <int N>
__device__ __forceinline__ void cp_wait() {
    asm volatile("cp.async.wait_group %0;\n" :: "n"(N));
}

// ================= async 3-stage fp16 GEMM core (ldmatrix) ================
// C[128x128] fp32 accum, A/B fp16 [row][k] global, k-tile 32.
// 256 threads = 8 warps 4(M)x2(N), warp tile 32x64.
// Smem row stride 40 halfs (80B): 16B-aligned cp.async dsts; ldmatrix rows at
// 20-word stride cover all 32 banks conflict-free.
// Steady state keeps TWO tile-loads in flight (wait_group<2>).
__device__ __forceinline__ void gemm_async_f16(
    const __half* __restrict__ Abase, int lda,
    const __half* __restrict__ Bbase, int ldb,
    int ktiles,
    __half (*As)[128][40], __half (*Bs)[128][40],
    float c[2][8][4], int tid)
{
    const int lane = tid & 31, warp = tid >> 5;
    const int wm = warp & 3, wn = warp >> 2;
    const int r0 = tid >> 2, h8 = (tid & 3) << 3;  // 8 halfs = 16 B per cp
    const int lrow = lane & 15, lcol = (lane >> 4) << 3;  // ldmatrix addressing

    auto issue = [&](int kt, int buf) {
        const int k0 = kt * 32;
        cp16(&As[buf][r0][h8],      Abase + (size_t)r0 * lda + k0 + h8);
        cp16(&As[buf][r0 + 64][h8], Abase + (size_t)(r0 + 64) * lda + k0 + h8);
        cp16(&Bs[buf][r0][h8],      Bbase + (size_t)r0 * ldb + k0 + h8);
        cp16(&Bs[buf][r0 + 64][h8], Bbase + (size_t)(r0 + 64) * ldb + k0 + h8);
        cp_commit();
    };

    issue(0, 0);
    issue(1, 1);
    for (int kt = 0; kt < ktiles; kt++) {
        const int buf = kt % NSTAGE;
        if (kt + 2 < ktiles)        { issue(kt + 2, (kt + 2) % NSTAGE); cp_wait<2>(); }
        else if (kt + 2 == ktiles)  { cp_wait<1>(); }
        else                        { cp_wait<0>(); }
        __syncthreads();

#pragma unroll
        for (int kk = 0; kk < 2; kk++) {
            const int kb = kk << 4;
            uint32_t a[2][4];
#pragma unroll
            for (int ms = 0; ms < 2; ms++) {
                int rb = wm * 32 + ms * 16;
                ldsm_x4(a[ms][0], a[ms][1], a[ms][2], a[ms][3],
                        &As[buf][rb + lrow][kb + lcol]);
            }
            uint32_t b[8][2];
#pragma unroll
            for (int g = 0; g < 4; g++) {
                int nb = wn * 64 + g * 16;
                uint32_t m0, m1, m2, m3;
                ldsm_x4(m0, m1, m2, m3, &Bs[buf][nb + lrow][kb + lcol]);
                b[2 * g][0]     = m0; b[2 * g][1]     = m2;
                b[2 * g + 1][0] = m1; b[2 * g + 1][1] = m3;
            }
#pragma unroll
            for (int ms = 0; ms < 2; ms++)
#pragma unroll
                for (int ns = 0; ns < 8; ns++)
                    mma_f16(c[ms][ns], a[ms], b[ns]);
        }
        __syncthreads();
    }
}

// ================= LDG+cvt tf32 GEMM core (external fp32 inputs) ==========
// B_KN=true : global B is [K][N] row-major (transposed while staging to smem)
template <bool B_KN>
__device__ __forceinline__ void gemm_main(
    const float* __restrict__ Abase, int lda,
    const float* __restrict__ Bbase, int ldb,
    int ktiles,
    uint32_t (*As)[20], uint32_t (*Bs)[20],
    float c[2][8][4], int tid)
{
    const int lane = tid & 31, warp = tid >> 5;
    const int gid = lane >> 2, tig = lane & 3;
    const int wm = warp & 3, wn = warp >> 2;

    for (int kt = 0; kt < ktiles; kt++) {
        const int k0 = kt * 16;
#pragma unroll
        for (int i = 0; i < 2; i++) {
            int t = tid + 256 * i;
            int row = t >> 2, c4 = (t & 3) << 2;
            float4 v = __ldg(reinterpret_cast<const float4*>(
                Abase + (size_t)row * lda + k0 + c4));
            As[row][c4 + 0] = f2tf32(v.x);
            As[row][c4 + 1] = f2tf32(v.y);
            As[row][c4 + 2] = f2tf32(v.z);
            As[row][c4 + 3] = f2tf32(v.w);
        }
        if (B_KN) {
#pragma unroll
            for (int i = 0; i < 2; i++) {
                int t = tid + 256 * i;
                int k = t >> 5, c4 = (t & 31) << 2;
                float4 v = __ldg(reinterpret_cast<const float4*>(
                    Bbase + (size_t)(k0 + k) * ldb + c4));
                Bs[c4 + 0][k] = f2tf32(v.x);
                Bs[c4 + 1][k] = f2tf32(v.y);
                Bs[c4 + 2][k] = f2tf32(v.z);
                Bs[c4 + 3][k] = f2tf32(v.w);
            }
        } else {
#pragma unroll
            for (int i = 0; i < 2; i++) {
                int t = tid + 256 * i;
                int row = t >> 2, c4 = (t & 3) << 2;
                float4 v = __ldg(reinterpret_cast<const float4*>(
                    Bbase + (size_t)row * ldb + k0 + c4));
                Bs[row][c4 + 0] = f2tf32(v.x);
                Bs[row][c4 + 1] = f2tf32(v.y);
                Bs[row][c4 + 2] = f2tf32(v.z);
                Bs[row][c4 + 3] = f2tf32(v.w);
            }
        }
        __syncthreads();

#pragma unroll
        for (int kk = 0; kk < 2; kk++) {
            const int kb = kk << 3;
            uint32_t a[2][4];
#pragma unroll
            for (int ms = 0; ms < 2; ms++) {
                int rb = wm * 32 + ms * 16;
                a[ms][0] = As[rb + gid][kb + tig];
                a[ms][1] = As[rb + gid + 8][kb + tig];
                a[ms][2] = As[rb + gid][kb + tig + 4];
                a[ms][3] = As[rb + gid + 8][kb + tig + 4];
            }
            uint32_t b[8][2];
#pragma unroll
            for (int ns = 0; ns < 8; ns++) {
                int nb = wn * 64 + ns * 8;
                b[ns][0] = Bs[nb + gid][kb + tig];
                b[ns][1] = Bs[nb + gid][kb + tig + 4];
            }
#pragma unroll
            for (int ms = 0; ms < 2; ms++)
#pragma unroll
                for (int ns = 0; ns < 8; ns++)
                    mma_tf32(c[ms][ns], a[ms], b[ns]);
        }
        __syncthreads();
    }
}

// ---------------- K1: QKV projection (stores fp16) ------------------------
// qkv[n,o,p] = fp16( sum_c Wqkv[o,c] * x[n,c,p] + bqkv[o] )
__global__ void __launch_bounds__(256, 2) k_qkv(
    const float* __restrict__ x, const float* __restrict__ Wqkv,
    const float* __restrict__ bqkv)
{
    __shared__ uint32_t As[128][20];
    __shared__ uint32_t Bs[128][20];
    const int n = blockIdx.z;
    const int m0 = blockIdx.y * 128;
    const int p0 = blockIdx.x * 128;
    const float* Abase = Wqkv + (size_t)m0 * C_IN;               // [M][K]
    const float* Bbase = x + (size_t)n * C_IN * HW + p0;         // [K][N]
    float c[2][8][4] = {};
    gemm_main<true>(Abase, C_IN, Bbase, HW, C_IN / 16, As, Bs, c, threadIdx.x);

    const int lane = threadIdx.x & 31, warp = threadIdx.x >> 5;
    const int gid = lane >> 2, tig = lane & 3, wm = warp & 3, wn = warp >> 2;
    __half* Cb = g_qkv + (size_t)n * OC * HW;
#pragma unroll
    for (int ms = 0; ms < 2; ms++) {
        const int r0 = m0 + wm * 32 + ms * 16 + gid;
        const float b0 = bqkv[r0], b1 = bqkv[r0 + 8];
#pragma unroll
        for (int ns = 0; ns < 8; ns++) {
            const int col = p0 + wn * 64 + ns * 8 + 2 * tig;
            *(__half2*)(Cb + (size_t)r0 * HW + col) =
                __halves2half2(__float2half_rn(c[ms][ns][0] + b0),
                               __float2half_rn(c[ms][ns][1] + b0));
            *(__half2*)(Cb + (size_t)(r0 + 8) * HW + col) =
                __halves2half2(__float2half_rn(c[ms][ns][2] + b1),
                               __float2half_rn(c[ms][ns][3] + b1));
        }
    }
}

// ---------------- K2: S' = fp16(exp(Q K^T / 64)), column partial sums -----
// Faithful reshape: Q[i,k] = qkv_flat[i*384 + k], K[j,k] = qkv_flat[j*384 + 128 + k]
// Epilogue stages the 128x128 fp16 tile through smem -> 16B coalesced STG.
__global__ void __launch_bounds__(256, 2) k_scores()
{
    extern __shared__ __align__(16) __half dynsm[];
    __half (*As)[128][40] = reinterpret_cast<__half (*)[128][40]>(dynsm);
    __half (*Bs)[128][40] = reinterpret_cast<__half (*)[128][40]>(dynsm + NSTAGE * 128 * 40);

    const int n = blockIdx.z;
    const int i0 = blockIdx.y * 128;
    const int j0 = blockIdx.x * 128;
    const __half* qb = g_qkv + (size_t)n * OC * HW;
    const __half* Abase = qb + (size_t)i0 * 384;          // Q rows  [M][K] ld 384
    const __half* Bbase = qb + (size_t)j0 * 384 + 128;    // K rows  [N][K] ld 384
    float c[2][8][4] = {};
    gemm_async_f16(Abase, 384, Bbase, 384, 128 / 32, As, Bs, c, threadIdx.x);

    const int tid = threadIdx.x;
    const int lane = tid & 31, warp = tid >> 5;
    const int gid = lane >> 2, tig = lane & 3, wm = warp & 3, wn = warp >> 2;
    const float scale = 0.015625f;  // 1/sqrt(4096)

    // staging views into the arena (mainloop done; last loop iter ended with sync)
    __half2* sm = reinterpret_cast<__half2*>(dynsm);          // [row][h2 col], stride 68 h2 (272 B)
    float* part = reinterpret_cast<float*>(sm + 128 * 68);    // 512 floats, disjoint from sm tile

    float csum[8][2];
#pragma unroll
    for (int ns = 0; ns < 8; ns++) { csum[ns][0] = 0.f; csum[ns][1] = 0.f; }

#pragma unroll
    for (int ms = 0; ms < 2; ms++) {
        const int row = wm * 32 + ms * 16 + gid;
#pragma unroll
        for (int ns = 0; ns < 8; ns++) {
            const int ch2 = wn * 32 + ns * 4 + tig;   // half2 column
            // round exp to fp16 HERE; colsum adds the ROUNDED values so the
            // normalization matches the stored matrix exactly.
            __half h0 = __float2half_rn(fexp(c[ms][ns][0] * scale));
            __half h1 = __float2half_rn(fexp(c[ms][ns][1] * scale));
            __half h2 = __float2half_rn(fexp(c[ms][ns][2] * scale));
            __half h3 = __float2half_rn(fexp(c[ms][ns][3] * scale));
            sm[row * 68 + ch2]       = __halves2half2(h0, h1);
            sm[(row + 8) * 68 + ch2] = __halves2half2(h2, h3);
            csum[ns][0] += __half2float(h0) + __half2float(h2);
            csum[ns][1] += __half2float(h1) + __half2float(h3);
        }
    }
    // deterministic column reduction: shfl across row-groups, smem across warps
#pragma unroll
    for (int ns = 0; ns < 8; ns++) {
#pragma unroll
        for (int jj = 0; jj < 2; jj++) {
            float v = csum[ns][jj];
            v += __shfl_xor_sync(0xffffffffu, v, 4);
            v += __shfl_xor_sync(0xffffffffu, v, 8);
            v += __shfl_xor_sync(0xffffffffu, v, 16);
            if (gid == 0)
                part[wm * 128 + wn * 64 + ns * 8 + 2 * tig + jj] = v;
        }
    }
    __syncthreads();

    // coalesced 16B stores: 2048 chunks of 8 halfs, 8 per thread
    __half* Sb = g_S + (size_t)n * HW * HW;
#pragma unroll
    for (int it = 0; it < 8; it++) {
        int q = it * 256 + tid;
        int row = q >> 4, ch = q & 15;
        float4 v = *reinterpret_cast<const float4*>(sm + row * 68 + ch * 4);
        *reinterpret_cast<float4*>(Sb + (size_t)(i0 + row) * HW + j0 + ch * 8) = v;
    }
    if (tid < 128) {
        float s = part[tid] + part[128 + tid] + part[256 + tid] + part[384 + tid];
        g_colpart[((size_t)n * 32 + blockIdx.y) * HW + j0 + tid] = s;
    }
}

// ---------------- K3: colsum reduce + VsT[d][j] = fp16(256*V[j,d]/colsum[j])
__global__ void k_vscale()
{
    __shared__ float ps[32][33];
    __shared__ float t[32][33];
    const int n = blockIdx.y;
    const int j0 = blockIdx.x * 32;
    const int tx = threadIdx.x, ty = threadIdx.y;

    // reduce the 32 per-i-block partials for columns j0..j0+31 (deterministic tree)
    ps[ty][tx] = g_colpart[((size_t)n * 32 + ty) * HW + j0 + tx];
    __syncthreads();
#pragma unroll
    for (int s = 16; s > 0; s >>= 1) {
        if (ty < s) ps[ty][tx] += ps[ty + s][tx];
        __syncthreads();
    }
    const float inv = VS_SCALE / ps[0][tx];   // for column j = j0 + tx

    const __half* qb = g_qkv + (size_t)n * OC * HW;
    __half* Vb = g_VsT + (size_t)n * E_DIM * HW;
#pragma unroll
    for (int dd = 0; dd < 4; dd++) {
        t[ty][tx] = __half2float(qb[(size_t)(j0 + ty) * 384 + 256 + dd * 32 + tx]);
        __syncthreads();
        Vb[(size_t)(dd * 32 + ty) * HW + j0 + tx] = __float2half_rn(t[tx][ty] * inv);
        __syncthreads();
    }
}

// ---------------- K4: O_partial = S' @ VsT^T (fp16 MMA, split-K x8) -------
__global__ void __launch_bounds__(256, 2) k_pv()
{
    extern __shared__ __align__(16) __half dynsm[];
    __half (*As)[128][40] = reinterpret_cast<__half (*)[128][40]>(dynsm);
    __half (*Bs)[128][40] = reinterpret_cast<__half (*)[128][40]>(dynsm + NSTAGE * 128 * 40);

    const int n = blockIdx.z;
    const int i0 = blockIdx.y * 128;
    const int split = blockIdx.x;
    const int jbase = split * (HW / KSPLIT);
    const __half* Abase = g_S + (size_t)n * HW * HW + (size_t)i0 * HW + jbase;
    const __half* Bbase = g_VsT + (size_t)n * E_DIM * HW + jbase;
    float c[2][8][4] = {};
    gemm_async_f16(Abase, HW, Bbase, HW, (HW / KSPLIT) / 32, As, Bs, c, threadIdx.x);

    const int lane = threadIdx.x & 31, warp = threadIdx.x >> 5;
    const int gid = lane >> 2, tig = lane & 3, wm = warp & 3, wn = warp >> 2;
    __half* Ob = g_Opart + ((size_t)split * N_BATCH + n) * HW * E_DIM;
#pragma unroll
    for (int ms = 0; ms < 2; ms++) {
        const int r0 = i0 + wm * 32 + ms * 16 + gid;
#pragma unroll
        for (int ns = 0; ns < 8; ns++) {
            const int col = wn * 64 + ns * 8 + 2 * tig;
            *(__half2*)(Ob + (size_t)r0 * E_DIM + col) =
                __halves2half2(__float2half_rn(c[ms][ns][0] * VS_INV),
                               __float2half_rn(c[ms][ns][1] * VS_INV));
            *(__half2*)(Ob + (size_t)(r0 + 8) * E_DIM + col) =
                __halves2half2(__float2half_rn(c[ms][ns][2] * VS_INV),
                               __float2half_rn(c[ms][ns][3] * VS_INV));
        }
    }
}

// ---------------- K5: output projection + split-K reduce ------------------
// y[n,c,p] = sum_e Wout[c,e] * (sum_s Opart_s)[n][e*4096 + p] + bout[c]
__global__ void __launch_bounds__(256, 2) k_proj(
    float* __restrict__ out, const float* __restrict__ Wout,
    const float* __restrict__ bout)
{
    __shared__ uint32_t As[128][20];
    __shared__ uint32_t Bs[128][20];
    const int n = blockIdx.z;
    const int c0 = blockIdx.y * 128;
    const int p0 = blockIdx.x * 128;
    const int tid = threadIdx.x;
    const float* Abase = Wout + (size_t)c0 * E_DIM;                               // [M][K] ld 128
    const __half* Bp0 = g_Opart + (size_t)n * HW * E_DIM + p0;                    // split stride:
    const size_t sstr = (size_t)N_BATCH * HW * E_DIM;                             // N_BATCH*HW*E

    const int lane = tid & 31, warp = tid >> 5;
    const int gid = lane >> 2, tig = lane & 3;
    const int wm = warp & 3, wn = warp >> 2;
    float c[2][8][4] = {};

    for (int kt = 0; kt < E_DIM / 16; kt++) {
        const int k0 = kt * 16;
#pragma unroll
        for (int i = 0; i < 2; i++) {
            int t = tid + 256 * i;
            int row = t >> 2, c4 = (t & 3) << 2;
            float4 v = __ldg(reinterpret_cast<const float4*>(
                Abase + (size_t)row * E_DIM + k0 + c4));
            As[row][c4 + 0] = f2tf32(v.x);
            As[row][c4 + 1] = f2tf32(v.y);
            As[row][c4 + 2] = f2tf32(v.z);
            As[row][c4 + 3] = f2tf32(v.w);
        }
#pragma unroll
        for (int i = 0; i < 2; i++) {
            int t = tid + 256 * i;
            int k = t >> 5, c4 = (t & 31) << 2;
            size_t off = (size_t)(k0 + k) * HW + c4;
            float s0 = 0.f, s1 = 0.f, s2 = 0.f, s3 = 0.f;
#pragma unroll
            for (int s = 0; s < KSPLIT; s++) {
                const __half* bp = Bp0 + s * sstr + off;
                __half2 p01 = *(const __half2*)(bp);
                __half2 p23 = *(const __half2*)(bp + 2);
                s0 += __half2float(p01.x); s1 += __half2float(p01.y);
                s2 += __half2float(p23.x); s3 += __half2float(p23.y);
            }
            Bs[c4 + 0][k] = f2tf32(s0);
            Bs[c4 + 1][k] = f2tf32(s1);
            Bs[c4 + 2][k] = f2tf32(s2);
            Bs[c4 + 3][k] = f2tf32(s3);
        }
        __syncthreads();

#pragma unroll
        for (int kk = 0; kk < 2; kk++) {
            const int kb = kk << 3;
            uint32_t a[2][4];
#pragma unroll
            for (int ms = 0; ms < 2; ms++) {
                int rb = wm * 32 + ms * 16;
                a[ms][0] = As[rb + gid][kb + tig];
                a[ms][1] = As[rb + gid + 8][kb + tig];
                a[ms][2] = As[rb + gid][kb + tig + 4];
                a[ms][3] = As[rb + gid + 8][kb + tig + 4];
            }
            uint32_t b[8][2];
#pragma unroll
            for (int ns = 0; ns < 8; ns++) {
                int nb = wn * 64 + ns * 8;
                b[ns][0] = Bs[nb + gid][kb + tig];
                b[ns][1] = Bs[nb + gid][kb + tig + 4];
            }
#pragma unroll
            for (int ms = 0; ms < 2; ms++)
#pragma unroll
                for (int ns = 0; ns < 8; ns++)
                    mma_tf32(c[ms][ns], a[ms], b[ns]);
        }
        __syncthreads();
    }

    float* Yb = out + (size_t)n * C_IN * HW;
#pragma unroll
    for (int ms = 0; ms < 2; ms++) {
        const int r0 = c0 + wm * 32 + ms * 16 + gid;
        const float b0 = bout[r0], b1 = bout[r0 + 8];
#pragma unroll
        for (int ns = 0; ns < 8; ns++) {
            const int col = p0 + wn * 64 + ns * 8 + 2 * tig;
            *(float2*)(Yb + (size_t)r0 * HW + col) =
                make_float2(c[ms][ns][0] + b0, c[ms][ns][1] + b0);
            *(float2*)(Yb + (size_t)(r0 + 8) * HW + col) =
                make_float2(c[ms][ns][2] + b1, c[ms][ns][3] + b1);
        }
    }
}

// ---------------- launch ---------------------------------------------------
extern "C" void kernel_launch(void* const* d_in, const int* in_sizes, int n_in,
                              void* d_out, int out_size)
{
    (void)in_sizes; (void)n_in; (void)out_size;
    const float* x    = (const float*)d_in[0];
    const float* Wqkv = (const float*)d_in[1];
    const float* bqkv = (const float*)d_in[2];
    const float* Wout = (const float*)d_in[3];
    const float* bout = (const float*)d_in[4];
    float* out = (float*)d_out;

    // raise dynamic-smem limit for the 3-stage kernels (attribute set, not an
    // allocation; idempotent — takes effect on the pre-capture correctness call)
    cudaFuncSetAttribute(k_scores, cudaFuncAttributeMaxDynamicSharedMemorySize, SMEM_DYN);
    cudaFuncSetAttribute(k_pv,     cudaFuncAttributeMaxDynamicSharedMemorySize, SMEM_DYN);

    dim3 blk(256);
    k_qkv<<<dim3(HW / 128, OC / 128, N_BATCH), blk>>>(x, Wqkv, bqkv);
    k_scores<<<dim3(HW / 128, HW / 128, N_BATCH), blk, SMEM_DYN>>>();
    k_vscale<<<dim3(HW / 32, N_BATCH), dim3(32, 32)>>>();
    k_pv<<<dim3(KSPLIT, HW / 128, N_BATCH), blk, SMEM_DYN>>>();
    k_proj<<<dim3(HW / 128, C_IN / 128, N_BATCH), blk>>>(out, Wout, bout);
}